// round 15
// baseline (speedup 1.0000x reference)
#include <cuda_runtime.h>
#include <math.h>
#include <stdint.h>

// ---------------- problem constants ----------------
#define S_    2048
#define NIMG_ 4
#define LI_   512
#define H_    16
#define DH_   64
#define DIM_  1024
#define BOT_  256
#define KSEL_ 256
#define IH_   4
#define ID_   16
#define GH_   8
#define NBUCK_ 129
#define FNEG  -1e30f

// ---------------- scratch (device globals; no runtime alloc) ----------------
__device__ float    g_tmp1[S_ * BOT_];
__device__ float    g_qkv [S_ * 3 * DIM_];
__device__ float    g_vt  [NIMG_ * H_ * DH_ * LI_];
__device__ float    g_qI  [S_ * 128];
__device__ float    g_kI  [S_ * 128];
__device__ float    g_scores[NIMG_ * LI_ * LI_];
__device__ unsigned g_selmask[S_ * 16];
__device__ float    g_attout[S_ * DIM_];
__device__ float    g_tmp2[S_ * BOT_];

// ---------------- helpers ----------------
__device__ __forceinline__ uint32_t smem_u32(const void* p) {
    uint32_t a;
    asm("{ .reg .u64 t; cvta.to.shared.u64 t, %1; cvt.u32.u64 %0, t; }" : "=r"(a) : "l"(p));
    return a;
}
__device__ __forceinline__ void cp_async16(uint32_t sa, const void* gp) {
    asm volatile("cp.async.cg.shared.global [%0], [%1], 16;" :: "r"(sa), "l"(gp) : "memory");
}
__device__ __forceinline__ uint32_t f2tf32(float v) {
    uint32_t u;
    asm("cvt.rna.tf32.f32 %0, %1;" : "=r"(u) : "f"(v));
    return u;
}
__device__ __forceinline__ void mma8(float* c, const uint32_t* a, const uint32_t* b) {
    asm volatile("mma.sync.aligned.m16n8k8.row.col.f32.tf32.tf32.f32 "
        "{%0,%1,%2,%3}, {%4,%5,%6,%7}, {%8,%9}, {%0,%1,%2,%3};"
        : "+f"(c[0]), "+f"(c[1]), "+f"(c[2]), "+f"(c[3])
        : "r"(a[0]), "r"(a[1]), "r"(a[2]), "r"(a[3]), "r"(b[0]), "r"(b[1]));
}

// FMA-pipe exp for x <= 0 (softmax value path). fast_exp(0) == 1.0f exactly.
__device__ __forceinline__ float fast_exp(float x) {
    x = fmaxf(x, -88.0f);
    float y = x * 1.44269504088896341f;
    float r = rintf(y);
    float f = y - r;
    float p = 1.53386867e-4f;
    p = fmaf(p, f, 1.33938769e-3f);
    p = fmaf(p, f, 9.61833251e-3f);
    p = fmaf(p, f, 5.55036329e-2f);
    p = fmaf(p, f, 2.40226452e-1f);
    p = fmaf(p, f, 6.93147182e-1f);
    p = fmaf(p, f, 1.0f);
    int ir = (int)r;
    float s = __int_as_float((ir + 127) << 23);
    return p * s;
}

// ======================================================================
// tf32 mma.sync GEMM (TN), NT=64 high-occupancy tile (validated R12).
// ======================================================================
#define AST 36

template<int NT>
__device__ __forceinline__ void load_chunk(
    const float* __restrict__ A, const float* __restrict__ B,
    int lda, int ldb, int m0, int n0, int k0,
    float* __restrict__ Abuf, float* __restrict__ Bbuf, int t)
{
    const int arow = t >> 3, ac4 = (t & 7) << 2;
    #pragma unroll
    for (int i = 0; i < 4; i++) {
        int row = arow + i * 32;
        cp_async16(smem_u32(Abuf + row * AST + ac4),
                   A + (long long)(m0 + row) * lda + k0 + ac4);
    }
    #pragma unroll
    for (int i = 0; i < NT / 32; i++) {
        int row = arow + i * 32;
        cp_async16(smem_u32(Bbuf + row * AST + ac4),
                   B + (long long)(n0 + row) * ldb + k0 + ac4);
    }
    asm volatile("cp.async.commit_group;" ::: "memory");
}

template<int MI, int NI>
__device__ __forceinline__ void compute_chunk(
    const float* __restrict__ Abuf, const float* __restrict__ Bbuf,
    int wm0, int wn0, int g, int l4, float (*acc)[4])
{
    #pragma unroll
    for (int ks = 0; ks < 4; ks++) {
        const int kk = ks * 8;
        uint32_t af[MI][4], bf[NI][2];
        #pragma unroll
        for (int mi = 0; mi < MI; mi++) {
            const float* p = Abuf + (wm0 + mi * 16 + g) * AST + kk + l4;
            af[mi][0] = f2tf32(p[0]);
            af[mi][2] = f2tf32(p[4]);
            af[mi][1] = f2tf32(p[8 * AST]);
            af[mi][3] = f2tf32(p[8 * AST + 4]);
        }
        #pragma unroll
        for (int ni = 0; ni < NI; ni++) {
            const float* p = Bbuf + (wn0 + ni * 8 + g) * AST + kk + l4;
            bf[ni][0] = f2tf32(p[0]);
            bf[ni][1] = f2tf32(p[4]);
        }
        #pragma unroll
        for (int mi = 0; mi < MI; mi++)
            #pragma unroll
            for (int ni = 0; ni < NI; ni++)
                mma8(acc[mi * NI + ni], af[mi], bf[ni]);
    }
}

template <int NT, int GM, int GN>
__global__ void __launch_bounds__(256, (NT == 64) ? 2 : 1) k_mma_gemm(
    const float* __restrict__ A, int lda,
    const float* __restrict__ B, int ldb,
    float* __restrict__ C, int ldc, int K,
    const float* __restrict__ bias, const float* __restrict__ scaler)
{
    constexpr int WM = 128 / GM, WN = NT / GN;
    constexpr int MI = WM / 16, NI = WN / 8;
    extern __shared__ float sm[];
    float* Abuf[2] = { sm, sm + 128 * AST };
    float* Bbuf[2] = { sm + 2 * 128 * AST, sm + 2 * 128 * AST + NT * AST };

    const int m0 = blockIdx.y * 128, n0 = blockIdx.x * NT;
    const int t = threadIdx.x, wid = t >> 5, lane = t & 31;
    const int wm0 = (wid % GM) * WM, wn0 = (wid / GM) * WN;
    const int g = lane >> 2, l4 = lane & 3;

    float acc[MI * NI][4];
    #pragma unroll
    for (int i = 0; i < MI * NI; i++)
        #pragma unroll
        for (int r = 0; r < 4; r++) acc[i][r] = 0.f;

    const int nch = K >> 5;
    load_chunk<NT>(A, B, lda, ldb, m0, n0, 0, Abuf[0], Bbuf[0], t);
    asm volatile("cp.async.wait_group 0;" ::: "memory");
    __syncthreads();

    for (int ch = 0; ch < nch; ch++) {
        const int cur = ch & 1;
        if (ch + 1 < nch)
            load_chunk<NT>(A, B, lda, ldb, m0, n0, (ch + 1) << 5, Abuf[cur ^ 1], Bbuf[cur ^ 1], t);
        compute_chunk<MI, NI>(Abuf[cur], Bbuf[cur], wm0, wn0, g, l4, acc);
        if (ch + 1 < nch) {
            asm volatile("cp.async.wait_group 0;" ::: "memory");
            __syncthreads();
        }
    }

    const float sc = scaler ? *scaler : 1.f;
    #pragma unroll
    for (int mi = 0; mi < MI; mi++) {
        const int r0 = m0 + wm0 + mi * 16 + g;
        #pragma unroll
        for (int ni = 0; ni < NI; ni++) {
            const int col = n0 + wn0 + ni * 8 + 2 * l4;
            float bx = 0.f, by = 0.f;
            if (bias) { bx = bias[col]; by = bias[col + 1]; }
            const float* a = acc[mi * NI + ni];
            float2 v0 = { (a[0] + bx) * sc, (a[1] + by) * sc };
            float2 v1 = { (a[2] + bx) * sc, (a[3] + by) * sc };
            *(float2*)&C[(long long)r0 * ldc + col] = v0;
            *(float2*)&C[(long long)(r0 + 8) * ldc + col] = v1;
        }
    }
}

// ======================================================================
// idxproj v2: 32x64 tiles (256 blocks), software-pipelined register
// prefetch (LDG for chunk k+1 issues before chunk-k FMAs). Per output
// element the k-accumulation order is unchanged -> bit-identical to the
// validated version; selection masks cannot move.
// ======================================================================
__global__ void __launch_bounds__(256) k_idxproj(
    const float* __restrict__ hs,
    const float* __restrict__ Wq, const float* __restrict__ Wk)
{
    __shared__ float As[16 * 36];   // [kk][row 0..31]
    __shared__ float Bs[16 * 68];   // [kk][col 0..63]
    const int t  = threadIdx.x;
    const int tx = t & 15, ty = t >> 4;
    const int m0 = blockIdx.y * 32;
    const int n0 = blockIdx.x * 64;
    const float* B = (n0 < 128) ? Wq : Wk;
    float* C = (n0 < 128) ? g_qI : g_kI;
    const int nb = n0 & 127;

    const int rA = t >> 2;            // 0..63 (A path uses t<128 -> 0..31)
    const int lk = (t & 3) << 2;
    const float* Ap = hs + (size_t)(m0 + (rA & 31)) * DIM_ + lk;
    const float* Bp = B + (size_t)(nb + rA) * DIM_ + lk;

    float4 av = make_float4(0.f, 0.f, 0.f, 0.f), bv;
    if (t < 128) av = *(const float4*)(Ap);
    bv = *(const float4*)(Bp);

    float acc[2][4] = {};
    for (int k0 = 0; k0 < DIM_; k0 += 16) {
        __syncthreads();
        if (t < 128) {
            As[(lk + 0) * 36 + rA] = av.x;
            As[(lk + 1) * 36 + rA] = av.y;
            As[(lk + 2) * 36 + rA] = av.z;
            As[(lk + 3) * 36 + rA] = av.w;
        }
        Bs[(lk + 0) * 68 + rA] = bv.x;
        Bs[(lk + 1) * 68 + rA] = bv.y;
        Bs[(lk + 2) * 68 + rA] = bv.z;
        Bs[(lk + 3) * 68 + rA] = bv.w;
        __syncthreads();
        if (k0 + 16 < DIM_) {   // prefetch next chunk while FMAs run
            if (t < 128) av = *(const float4*)(Ap + k0 + 16);
            bv = *(const float4*)(Bp + k0 + 16);
        }
        #pragma unroll
        for (int kk = 0; kk < 16; kk++) {
            float a0 = As[kk * 36 + 2 * ty];
            float a1 = As[kk * 36 + 2 * ty + 1];
            float4 b = *(const float4*)&Bs[kk * 68 + 4 * tx];
            acc[0][0] = fmaf(a0, b.x, acc[0][0]);
            acc[0][1] = fmaf(a0, b.y, acc[0][1]);
            acc[0][2] = fmaf(a0, b.z, acc[0][2]);
            acc[0][3] = fmaf(a0, b.w, acc[0][3]);
            acc[1][0] = fmaf(a1, b.x, acc[1][0]);
            acc[1][1] = fmaf(a1, b.y, acc[1][1]);
            acc[1][2] = fmaf(a1, b.z, acc[1][2]);
            acc[1][3] = fmaf(a1, b.w, acc[1][3]);
        }
    }
    const int m = m0 + 2 * ty;
    *(float4*)&C[(size_t)m * 128 + nb + 4 * tx] =
        make_float4(acc[0][0], acc[0][1], acc[0][2], acc[0][3]);
    *(float4*)&C[(size_t)(m + 1) * 128 + nb + 4 * tx] =
        make_float4(acc[1][0], acc[1][1], acc[1][2], acc[1][3]);
}

// ======================================================================
// Index scores v3.1 (validated round 14).
// ======================================================================
__global__ void __launch_bounds__(256, 2) k_idx_scores(
    const int* __restrict__ coords,
    const float* __restrict__ W1g, const float* __restrict__ b1g,
    const float* __restrict__ W2g, const float* __restrict__ b2g,
    const float* __restrict__ rpe_table)
{
    extern __shared__ float dsm[];
    float* Ks   = dsm;
    float* qrow = dsm + 128 * 128;
    float* rpes = qrow + 8 * 128;
    float* w1s  = rpes + 520;
    float* w2s  = w1s + 32;
    float* b1s  = w2s + 32;
    float* b2s  = b1s + 8;
    int*   poss = (int*)(b2s + 4);
    int*   posq = poss + 512;

    const int qb   = blockIdx.x;
    const int img  = qb >> 6;
    const int gq0  = qb * 8;
    const int base = img << 9;
    const int t = threadIdx.x;
    const int q2 = t >> 6;
    const int kk = t & 63;

    {
        int q = t >> 5, c4 = (t & 31) << 2;
        *(float4*)&qrow[q * 128 + c4] = *(const float4*)&g_qI[(size_t)(gq0 + q) * 128 + c4];
    }
    for (int i = t; i < NBUCK_ * IH_; i += 256) rpes[i] = rpe_table[i];
    if (t < 32) w1s[t] = W1g[t];
    else if (t < 64) w2s[t - 32] = W2g[t - 32];
    else if (t < 72) b1s[t - 64] = b1g[t - 64];
    else if (t < 76) b2s[t - 72] = b2g[t - 72];
    else if (t >= 128 && t < 136) posq[t - 128] = coords[(size_t)(gq0 + t - 128) * 2 + 1];
    for (int i = t; i < LI_; i += 256) poss[i] = coords[(size_t)(base + i) * 2 + 1];
    __syncthreads();

    float* outbase = g_scores + (size_t)img * LI_ * LI_;
    const int q0l = (qb & 63) * 8 + q2 * 2;
    const int posq0 = posq[q2 * 2], posq1 = posq[q2 * 2 + 1];
    const float* qr0 = qrow + (q2 * 2) * 128;
    const float* qr1 = qr0 + 128;

    for (int w = 0; w < 4; w++) {
        #pragma unroll
        for (int i = 0; i < 16; i++) {
            int fid = i * 256 + t;
            int row = fid >> 5, c4 = fid & 31;
            int c4s = c4 ^ (row & 31);
            cp_async16(smem_u32(Ks + row * 128 + c4s * 4),
                       g_kI + (size_t)(base + w * 128 + row) * 128 + c4 * 4);
        }
        asm volatile("cp.async.commit_group;" ::: "memory");
        asm volatile("cp.async.wait_group 0;" ::: "memory");
        __syncthreads();

        const float* kr0 = Ks + kk * 128;
        const float* kr1 = Ks + (kk + 64) * 128;
        const int kswz = kk & 31;

        float dot[2][2][8];
        #pragma unroll
        for (int h = 0; h < 8; h++) {
            float d00 = 0.f, d01 = 0.f, d10 = 0.f, d11 = 0.f;
            #pragma unroll
            for (int j = 0; j < 4; j++) {
                int c4 = h * 4 + j;
                float4 b0 = *(const float4*)&kr0[(c4 ^ kswz) * 4];
                float4 b1 = *(const float4*)&kr1[(c4 ^ kswz) * 4];
                float4 a0 = *(const float4*)&qr0[c4 * 4];
                float4 a1 = *(const float4*)&qr1[c4 * 4];
                d00 += a0.x*b0.x + a0.y*b0.y + a0.z*b0.z + a0.w*b0.w;
                d01 += a1.x*b0.x + a1.y*b0.y + a1.z*b0.z + a1.w*b0.w;
                d10 += a0.x*b1.x + a0.y*b1.y + a0.z*b1.z + a0.w*b1.w;
                d11 += a1.x*b1.x + a1.y*b1.y + a1.z*b1.z + a1.w*b1.w;
            }
            dot[0][0][h] = d00; dot[0][1][h] = d01;
            dot[1][0][h] = d10; dot[1][1][h] = d11;
        }

        #pragma unroll
        for (int kq = 0; kq < 2; kq++) {
            const int kglob = w * 128 + kk + kq * 64;
            const int pk = poss[kglob];
            #pragma unroll
            for (int qq = 0; qq < 2; qq++) {
                int rel = (qq ? posq1 : posq0) - pk;
                rel = rel < -64 ? -64 : (rel > 64 ? 64 : rel);
                const float* rp = &rpes[(rel + 64) * IH_];
                float xg[IH_];
                #pragma unroll
                for (int i = 0; i < IH_; i++) xg[i] = dot[kq][qq][IH_ + i] + rp[i];
                float hg[GH_];
                #pragma unroll
                for (int j = 0; j < GH_; j++) {
                    float s = b1s[j];
                    #pragma unroll
                    for (int i = 0; i < IH_; i++) s = fmaf(w1s[j * IH_ + i], xg[i], s);
                    hg[j] = fmaxf(s, 0.f);
                }
                float score = 0.f;
                #pragma unroll
                for (int i = 0; i < IH_; i++) {
                    float s = b2s[i];
                    #pragma unroll
                    for (int j = 0; j < GH_; j++) s = fmaf(w2s[i * GH_ + j], hg[j], s);
                    float gi = 1.f / (1.f + expf(-s));
                    float rs = fmaxf(dot[kq][qq][i] + rp[i], 0.f);
                    score = fmaf(rs, gi, score);
                }
                outbase[(size_t)(q0l + qq) * LI_ + kglob] = score;
            }
        }
        __syncthreads();
    }
}

// ======================================================================
// Exact top-K (validated round 8).
// ======================================================================
__global__ void __launch_bounds__(256) k_topk()
{
    int row  = blockIdx.x;
    int img  = row >> 9;
    const float* sc = g_scores + (size_t)img * LI_ * LI_ + (size_t)(row & 511) * LI_;
    __shared__ unsigned skeys[LI_];
    __shared__ unsigned hist[257];
    __shared__ unsigned mwords[16];
    __shared__ unsigned short eqidx[LI_];
    __shared__ unsigned s_prefix, s_kth, s_eqcnt;
    int t = threadIdx.x;

    for (int i = t; i < LI_; i += 256) {
        unsigned u = __float_as_uint(sc[i]);
        u = (u & 0x80000000u) ? ~u : (u | 0x80000000u);
        skeys[i] = u;
    }
    if (t == 0) { s_prefix = 0; s_kth = KSEL_; s_eqcnt = 0; }
    if (t < 16) mwords[t] = 0;
    __syncthreads();

    unsigned prefmask = 0;
    for (int r = 0; r < 4; r++) {
        int shift = 24 - 8 * r;
        hist[t] = 0;
        if (t == 0) hist[256] = 0;
        __syncthreads();
        unsigned pref = s_prefix, kth = s_kth;
        for (int i = t; i < LI_; i += 256) {
            unsigned u = skeys[i];
            if ((u & prefmask) == pref) atomicAdd(&hist[(u >> shift) & 255], 1u);
        }
        __syncthreads();
        #pragma unroll
        for (int off = 1; off < 256; off <<= 1) {
            unsigned add = (t + off < 256) ? hist[t + off] : 0u;
            __syncthreads();
            hist[t] += add;
            __syncthreads();
        }
        unsigned sfx = hist[t];
        unsigned nx  = hist[t + 1];
        if (sfx >= kth && nx < kth) {
            s_kth    = kth - nx;
            s_prefix = pref | ((unsigned)t << shift);
        }
        prefmask |= (0xFFu << shift);
        __syncthreads();
    }
    unsigned tau = s_prefix;

    for (int i = t; i < LI_; i += 256) {
        unsigned u = skeys[i];
        if (u > tau) {
            atomicOr(&mwords[i >> 5], 1u << (i & 31));
        } else if (u == tau) {
            unsigned p = atomicAdd(&s_eqcnt, 1u);
            eqidx[p] = (unsigned short)i;
        }
    }
    __syncthreads();
    if (t == 0) {
        int cg = 0;
        #pragma unroll
        for (int w = 0; w < 16; w++) cg += __popc(mwords[w]);
        int need = KSEL_ - cg;
        int ce = (int)s_eqcnt;
        if (need > 0) {
            if (ce <= need) {
                for (int j = 0; j < ce; j++) { int i = eqidx[j]; mwords[i >> 5] |= 1u << (i & 31); }
            } else {
                for (int a = 1; a < ce; a++) {
                    unsigned short v = eqidx[a]; int b = a - 1;
                    while (b >= 0 && eqidx[b] > v) { eqidx[b + 1] = eqidx[b]; b--; }
                    eqidx[b + 1] = v;
                }
                for (int j = 0; j < need; j++) { int i = eqidx[j]; mwords[i >> 5] |= 1u << (i & 31); }
            }
        }
    }
    __syncthreads();
    if (t < 16) g_selmask[(size_t)row * 16 + t] = mwords[t];
}

// ======================================================================
// Fused flash attention (validated round 14).
// ======================================================================
__global__ void __launch_bounds__(256, 2) k_flash()
{
    extern __shared__ float sm[];
    float* Qs  = sm;
    float* Ks  = Qs + 128 * 68;
    float* VTs = Ks + 64 * 68;
    unsigned* mskS = (unsigned*)(VTs + 64 * 68);

    const int qt = blockIdx.x, z = blockIdx.y;
    const int img = z >> 4, h = z & 15;
    const int t = threadIdx.x, w = t >> 5, lane = t & 31;
    const int g = lane >> 2, l4 = lane & 3;
    const int qrow0 = img * 512 + qt * 128;

    const float* Qg  = g_qkv + (size_t)qrow0 * 3072 + h * 64;
    const float* Kg0 = g_qkv + (size_t)img * 512 * 3072 + 1024 + h * 64;
    const float* VTg = g_vt + (size_t)z * (DH_ * LI_);

    #pragma unroll
    for (int i = 0; i < 8; i++) {
        int fid = t + i * 256;
        int row = fid >> 4, c4 = (fid & 15) << 2;
        cp_async16(smem_u32(Qs + row * 68 + c4), Qg + (size_t)row * 3072 + c4);
    }
    asm volatile("cp.async.commit_group;" ::: "memory");
    #pragma unroll
    for (int i = 0; i < 8; i++) {
        int widx = t + i * 256;
        mskS[widx] = g_selmask[(size_t)qrow0 * 16 + widx];
    }
    asm volatile("cp.async.wait_group 0;" ::: "memory");
    __syncthreads();

    const int rA = w * 16 + g, rB = rA + 8;

    uint32_t qf[8][4];
    #pragma unroll
    for (int kk = 0; kk < 8; kk++) {
        const float* ap = Qs + kk * 8 + l4;
        qf[kk][0] = f2tf32(ap[rA * 68]);
        qf[kk][1] = f2tf32(ap[rB * 68]);
        qf[kk][2] = f2tf32(ap[rA * 68 + 4]);
        qf[kk][3] = f2tf32(ap[rB * 68 + 4]);
    }

    float mrow0 = FNEG, mrow1 = FNEG, lrow0 = 0.f, lrow1 = 0.f;
    float oacc[8][4];
    #pragma unroll
    for (int i = 0; i < 8; i++)
        #pragma unroll
        for (int r = 0; r < 4; r++) oacc[i][r] = 0.f;

    for (int kt = 0; kt < 8; kt++) {
        const float* Kg = Kg0 + (size_t)(kt * 64) * 3072;
        #pragma unroll
        for (int i = 0; i < 4; i++) {
            int fid = t + i * 256;
            int row = fid >> 4, c4 = (fid & 15) << 2;
            cp_async16(smem_u32(Ks + row * 68 + c4), Kg + (size_t)row * 3072 + c4);
        }
        asm volatile("cp.async.commit_group;" ::: "memory");
        #pragma unroll
        for (int i = 0; i < 4; i++) {
            int fid = t + i * 256;
            int row = fid >> 4, c4 = (fid & 15) << 2;
            cp_async16(smem_u32(VTs + row * 68 + c4), VTg + (size_t)row * 512 + kt * 64 + c4);
        }
        asm volatile("cp.async.commit_group;" ::: "memory");
        asm volatile("cp.async.wait_group 1;" ::: "memory");
        __syncthreads();

        float sacc[8][4];
        #pragma unroll
        for (int i = 0; i < 8; i++)
            #pragma unroll
            for (int r = 0; r < 4; r++) sacc[i][r] = 0.f;
        #pragma unroll
        for (int kk = 0; kk < 8; kk++) {
            #pragma unroll
            for (int ni = 0; ni < 8; ni++) {
                const float* bp = Ks + (ni * 8 + g) * 68 + kk * 8 + l4;
                uint32_t bf[2] = { f2tf32(bp[0]), f2tf32(bp[4]) };
                mma8(sacc[ni], qf[kk], bf);
            }
        }

        float mx0 = FNEG, mx1 = FNEG;
        #pragma unroll
        for (int ni = 0; ni < 8; ni++) {
            int col = ni * 8 + 2 * l4;
            int wI = (kt << 1) + (col >> 5), bI = col & 31;
            unsigned mwA = mskS[rA * 16 + wI];
            unsigned mwB = mskS[rB * 16 + wI];
            float v0 = ((mwA >> bI) & 1u)       ? sacc[ni][0] * 0.125f : FNEG;
            float v1 = ((mwA >> (bI + 1)) & 1u) ? sacc[ni][1] * 0.125f : FNEG;
            float v2 = ((mwB >> bI) & 1u)       ? sacc[ni][2] * 0.125f : FNEG;
            float v3 = ((mwB >> (bI + 1)) & 1u) ? sacc[ni][3] * 0.125f : FNEG;
            sacc[ni][0] = v0; sacc[ni][1] = v1; sacc[ni][2] = v2; sacc[ni][3] = v3;
            mx0 = fmaxf(mx0, fmaxf(v0, v1));
            mx1 = fmaxf(mx1, fmaxf(v2, v3));
        }
        mx0 = fmaxf(mx0, __shfl_xor_sync(0xffffffffu, mx0, 1));
        mx0 = fmaxf(mx0, __shfl_xor_sync(0xffffffffu, mx0, 2));
        mx1 = fmaxf(mx1, __shfl_xor_sync(0xffffffffu, mx1, 1));
        mx1 = fmaxf(mx1, __shfl_xor_sync(0xffffffffu, mx1, 2));

        float mn0 = fmaxf(mrow0, mx0), mn1 = fmaxf(mrow1, mx1);
        float al0 = fast_exp(mrow0 - mn0), al1 = fast_exp(mrow1 - mn1);
        float pvd0 = (mn0 > -1e29f) ? 1.f : 0.f;
        float pvd1 = (mn1 > -1e29f) ? 1.f : 0.f;

        float ps0 = 0.f, ps1 = 0.f;
        #pragma unroll
        for (int ni = 0; ni < 8; ni++) {
            float p0 = fast_exp(sacc[ni][0] - mn0) * pvd0;
            float p1 = fast_exp(sacc[ni][1] - mn0) * pvd0;
            float p2 = fast_exp(sacc[ni][2] - mn1) * pvd1;
            float p3 = fast_exp(sacc[ni][3] - mn1) * pvd1;
            ps0 += p0 + p1; ps1 += p2 + p3;
            sacc[ni][0] = p0; sacc[ni][1] = p1; sacc[ni][2] = p2; sacc[ni][3] = p3;
        }
        ps0 += __shfl_xor_sync(0xffffffffu, ps0, 1);
        ps0 += __shfl_xor_sync(0xffffffffu, ps0, 2);
        ps1 += __shfl_xor_sync(0xffffffffu, ps1, 1);
        ps1 += __shfl_xor_sync(0xffffffffu, ps1, 2);
        lrow0 = lrow0 * al0 + ps0;
        lrow1 = lrow1 * al1 + ps1;
        mrow0 = mn0; mrow1 = mn1;
        #pragma unroll
        for (int i = 0; i < 8; i++) {
            oacc[i][0] *= al0; oacc[i][1] *= al0;
            oacc[i][2] *= al1; oacc[i][3] *= al1;
        }

        asm volatile("cp.async.wait_group 0;" ::: "memory");
        __syncthreads();

        const int src0 = (lane & ~3) | (l4 >> 1);
        const int src1 = src0 + 2;
        const bool odd = (l4 & 1);
        #pragma unroll
        for (int kk = 0; kk < 8; kk++) {
            const float* p = sacc[kk];
            float x0 = __shfl_sync(0xffffffffu, p[0], src0);
            float x1 = __shfl_sync(0xffffffffu, p[1], src0);
            float y0 = __shfl_sync(0xffffffffu, p[2], src0);
            float y1 = __shfl_sync(0xffffffffu, p[3], src0);
            float u0 = __shfl_sync(0xffffffffu, p[0], src1);
            float u1 = __shfl_sync(0xffffffffu, p[1], src1);
            float v0 = __shfl_sync(0xffffffffu, p[2], src1);
            float v1 = __shfl_sync(0xffffffffu, p[3], src1);
            uint32_t af[4] = { f2tf32(odd ? x1 : x0), f2tf32(odd ? y1 : y0),
                               f2tf32(odd ? u1 : u0), f2tf32(odd ? v1 : v0) };
            #pragma unroll
            for (int ni = 0; ni < 8; ni++) {
                const float* bp = VTs + (ni * 8 + g) * 68 + kk * 8 + l4;
                uint32_t bf[2] = { f2tf32(bp[0]), f2tf32(bp[4]) };
                mma8(oacc[ni], af, bf);
            }
        }
        __syncthreads();
    }

    const float inv0 = 1.f / lrow0, inv1 = 1.f / lrow1;
    float* OA = g_attout + (size_t)(qrow0 + rA) * DIM_ + h * 64;
    float* OB = g_attout + (size_t)(qrow0 + rB) * DIM_ + h * 64;
    #pragma unroll
    for (int ni = 0; ni < 8; ni++) {
        int col = ni * 8 + 2 * l4;
        *(float2*)&OA[col] = make_float2(oacc[ni][0] * inv0, oacc[ni][1] * inv0);
        *(float2*)&OB[col] = make_float2(oacc[ni][2] * inv1, oacc[ni][3] * inv1);
    }
}

// ======================================================================
// V transpose
// ======================================================================
__global__ void k_vt()
{
    __shared__ float s[32][65];
    const int z = blockIdx.x, kb = blockIdx.y;
    const int img = z >> 4, h = z & 15;
    const int t = threadIdx.x;
    const float* V = g_qkv + (size_t)img * LI_ * 3072 + 2048 + h * 64;
    const int kk = t >> 6, d = t & 63;
    #pragma unroll
    for (int i = 0; i < 8; i++) {
        int k = kb * 32 + kk + i * 4;
        s[kk + i * 4][d] = V[(size_t)k * 3072 + d];
    }
    __syncthreads();
    float* out = g_vt + (size_t)z * (DH_ * LI_) + kb * 32;
    const int ko = t & 31, dw = t >> 5;
    #pragma unroll
    for (int i = 0; i < 8; i++) {
        int dd = dw + i * 8;
        out[(size_t)dd * LI_ + ko] = s[ko][dd];
    }
}

// ======================================================================
// RoPE
// ======================================================================
__global__ void k_rope(const float* __restrict__ rope)
{
    __shared__ float cs[32], sns[32];
    int s = blockIdx.x;
    int t = threadIdx.x;
    if (t < 32) {
        float ang = rope[(size_t)s * 32 + t];
        cs[t] = cosf(ang);
        sns[t] = sinf(ang);
    }
    __syncthreads();
    int h = t >> 5, d = t & 31;
    float c = cs[d], sn = sns[d];
    float* q = g_qkv + (size_t)s * 3072 + h * 64;
    float* k = q + 1024;
    float q1 = q[d], q2 = q[d + 32];
    q[d]      = q1 * c - q2 * sn;
    q[d + 32] = q2 * c + q1 * sn;
    float k1 = k[d], k2 = k[d + 32];
    k[d]      = k1 * c - k2 * sn;
    k[d + 32] = k2 * c + k1 * sn;
}

// ======================================================================
// Launch: parallel chains. Code order: launch #4 = k_idxproj (ncu slot).
// ======================================================================
extern "C" void kernel_launch(void* const* d_in, const int* in_sizes, int n_in,
                              void* d_out, int out_size)
{
    const float* hs     = (const float*)d_in[0];
    const int*   coords = (const int*)  d_in[1];
    const float* rope   = (const float*)d_in[3];
    const float* Wq_idx = (const float*)d_in[4];
    const float* Wk_idx = (const float*)d_in[5];
    const float* W1g    = (const float*)d_in[6];
    const float* b1g    = (const float*)d_in[7];
    const float* W2g    = (const float*)d_in[8];
    const float* b2g    = (const float*)d_in[9];
    const float* rpe    = (const float*)d_in[10];
    const float* Wqkv_d = (const float*)d_in[11];
    const float* bqkv_d = (const float*)d_in[12];
    const float* Wqkv_u = (const float*)d_in[13];
    const float* bqkv_u = (const float*)d_in[14];
    const float* Wp_d   = (const float*)d_in[15];
    const float* bp_d   = (const float*)d_in[16];
    const float* Wp_u   = (const float*)d_in[17];
    const float* bp_u   = (const float*)d_in[18];
    const float* scaler = (const float*)d_in[19];
    float* out = (float*)d_out;

    float *tmp1, *qkv, *attout, *tmp2;
    cudaGetSymbolAddress((void**)&tmp1,   g_tmp1);
    cudaGetSymbolAddress((void**)&qkv,    g_qkv);
    cudaGetSymbolAddress((void**)&attout, g_attout);
    cudaGetSymbolAddress((void**)&tmp2,   g_tmp2);

    const int dyn64  = (2 * 128 + 2 * 64)  * AST * 4;
    const int dynFl  = (128 * 68 + 64 * 68 + 64 * 68) * 4 + 128 * 16 * 4;
    const int dynIS  = (128 * 128 + 8 * 128 + 520 + 32 + 32 + 8 + 4) * 4 + 512 * 4 + 8 * 4;
    cudaFuncSetAttribute((const void*)k_mma_gemm<64,4,2>,  cudaFuncAttributeMaxDynamicSharedMemorySize, dyn64);
    cudaFuncSetAttribute((const void*)k_flash, cudaFuncAttributeMaxDynamicSharedMemorySize, dynFl);
    cudaFuncSetAttribute((const void*)k_idx_scores, cudaFuncAttributeMaxDynamicSharedMemorySize, dynIS);

    static cudaStream_t sB = [](){
        cudaStream_t s; cudaStreamCreateWithFlags(&s, cudaStreamNonBlocking); return s;
    }();
    static cudaEvent_t eFork = [](){
        cudaEvent_t e; cudaEventCreateWithFlags(&e, cudaEventDisableTiming); return e;
    }();
    static cudaEvent_t eJoin = [](){
        cudaEvent_t e; cudaEventCreateWithFlags(&e, cudaEventDisableTiming); return e;
    }();

    cudaEventRecord(eFork, 0);
    cudaStreamWaitEvent(sB, eFork, 0);

    // (1-3) chain B
    k_mma_gemm<64,4,2><<<dim3(4, 16), 256, dyn64, sB>>>(
        hs, DIM_, Wqkv_d, DIM_, tmp1, BOT_, DIM_, bqkv_d, nullptr);
    k_mma_gemm<64,4,2><<<dim3(48, 16), 256, dyn64, sB>>>(
        tmp1, BOT_, Wqkv_u, BOT_, qkv, 3 * DIM_, BOT_, bqkv_u, nullptr);
    k_vt<<<dim3(NIMG_ * H_, 16), 256, 0, sB>>>();
    // (4) chain A: idx projections v2  <-- ncu measurement slot
    k_idxproj<<<dim3(4, 64), 256>>>(hs, Wq_idx, Wk_idx);
    // (5) chain B
    k_rope<<<S_, 512, 0, sB>>>(rope);
    // (6-7) chain A
    k_idx_scores<<<256, 256, dynIS>>>(coords, W1g, b1g, W2g, b2g, rpe);
    k_topk<<<S_, 256>>>();

    cudaEventRecord(eJoin, sB);
    cudaStreamWaitEvent(0, eJoin, 0);

    // flash
    k_flash<<<dim3(4, NIMG_ * H_), 256, dynFl>>>();

    // final projections
    k_mma_gemm<64,4,2><<<dim3(4, 16), 256, dyn64>>>(
        attout, DIM_, Wp_d, DIM_, tmp2, BOT_, DIM_, bp_d, nullptr);
    k_mma_gemm<64,4,2><<<dim3(16, 16), 256, dyn64>>>(
        tmp2, BOT_, Wp_u, BOT_, out, DIM_, BOT_, bp_u, scaler);
}

// round 16
// speedup vs baseline: 1.0775x; 1.0775x over previous
#include <cuda_runtime.h>
#include <math.h>
#include <stdint.h>

// ---------------- problem constants ----------------
#define S_    2048
#define NIMG_ 4
#define LI_   512
#define H_    16
#define DH_   64
#define DIM_  1024
#define BOT_  256
#define KSEL_ 256
#define IH_   4
#define ID_   16
#define GH_   8
#define NBUCK_ 129
#define FNEG  -1e30f

// ---------------- scratch (device globals; no runtime alloc) ----------------
__device__ float    g_tmp1[S_ * BOT_];
__device__ float    g_qkv [S_ * 3 * DIM_];
__device__ float    g_vt  [NIMG_ * H_ * DH_ * LI_];
__device__ float    g_qI  [S_ * 128];
__device__ float    g_kI  [S_ * 128];
__device__ float    g_scores[NIMG_ * LI_ * LI_];
__device__ unsigned g_selmask[S_ * 16];
__device__ float    g_attout[S_ * DIM_];
__device__ float    g_tmp2[S_ * BOT_];

// ---------------- helpers ----------------
__device__ __forceinline__ uint32_t smem_u32(const void* p) {
    uint32_t a;
    asm("{ .reg .u64 t; cvta.to.shared.u64 t, %1; cvt.u32.u64 %0, t; }" : "=r"(a) : "l"(p));
    return a;
}
__device__ __forceinline__ void cp_async16(uint32_t sa, const void* gp) {
    asm volatile("cp.async.cg.shared.global [%0], [%1], 16;" :: "r"(sa), "l"(gp) : "memory");
}
__device__ __forceinline__ uint32_t f2tf32(float v) {
    uint32_t u;
    asm("cvt.rna.tf32.f32 %0, %1;" : "=r"(u) : "f"(v));
    return u;
}
__device__ __forceinline__ void mma8(float* c, const uint32_t* a, const uint32_t* b) {
    asm volatile("mma.sync.aligned.m16n8k8.row.col.f32.tf32.tf32.f32 "
        "{%0,%1,%2,%3}, {%4,%5,%6,%7}, {%8,%9}, {%0,%1,%2,%3};"
        : "+f"(c[0]), "+f"(c[1]), "+f"(c[2]), "+f"(c[3])
        : "r"(a[0]), "r"(a[1]), "r"(a[2]), "r"(a[3]), "r"(b[0]), "r"(b[1]));
}

// FMA-pipe exp for x <= 0 (softmax value path). fast_exp(0) == 1.0f exactly.
__device__ __forceinline__ float fast_exp(float x) {
    x = fmaxf(x, -88.0f);
    float y = x * 1.44269504088896341f;
    float r = rintf(y);
    float f = y - r;
    float p = 1.53386867e-4f;
    p = fmaf(p, f, 1.33938769e-3f);
    p = fmaf(p, f, 9.61833251e-3f);
    p = fmaf(p, f, 5.55036329e-2f);
    p = fmaf(p, f, 2.40226452e-1f);
    p = fmaf(p, f, 6.93147182e-1f);
    p = fmaf(p, f, 1.0f);
    int ir = (int)r;
    float s = __int_as_float((ir + 127) << 23);
    return p * s;
}

// ======================================================================
// tf32 mma.sync GEMM (TN), NT=64 high-occupancy tile (validated R12).
// ======================================================================
#define AST 36

template<int NT>
__device__ __forceinline__ void load_chunk(
    const float* __restrict__ A, const float* __restrict__ B,
    int lda, int ldb, int m0, int n0, int k0,
    float* __restrict__ Abuf, float* __restrict__ Bbuf, int t)
{
    const int arow = t >> 3, ac4 = (t & 7) << 2;
    #pragma unroll
    for (int i = 0; i < 4; i++) {
        int row = arow + i * 32;
        cp_async16(smem_u32(Abuf + row * AST + ac4),
                   A + (long long)(m0 + row) * lda + k0 + ac4);
    }
    #pragma unroll
    for (int i = 0; i < NT / 32; i++) {
        int row = arow + i * 32;
        cp_async16(smem_u32(Bbuf + row * AST + ac4),
                   B + (long long)(n0 + row) * ldb + k0 + ac4);
    }
    asm volatile("cp.async.commit_group;" ::: "memory");
}

template<int MI, int NI>
__device__ __forceinline__ void compute_chunk(
    const float* __restrict__ Abuf, const float* __restrict__ Bbuf,
    int wm0, int wn0, int g, int l4, float (*acc)[4])
{
    #pragma unroll
    for (int ks = 0; ks < 4; ks++) {
        const int kk = ks * 8;
        uint32_t af[MI][4], bf[NI][2];
        #pragma unroll
        for (int mi = 0; mi < MI; mi++) {
            const float* p = Abuf + (wm0 + mi * 16 + g) * AST + kk + l4;
            af[mi][0] = f2tf32(p[0]);
            af[mi][2] = f2tf32(p[4]);
            af[mi][1] = f2tf32(p[8 * AST]);
            af[mi][3] = f2tf32(p[8 * AST + 4]);
        }
        #pragma unroll
        for (int ni = 0; ni < NI; ni++) {
            const float* p = Bbuf + (wn0 + ni * 8 + g) * AST + kk + l4;
            bf[ni][0] = f2tf32(p[0]);
            bf[ni][1] = f2tf32(p[4]);
        }
        #pragma unroll
        for (int mi = 0; mi < MI; mi++)
            #pragma unroll
            for (int ni = 0; ni < NI; ni++)
                mma8(acc[mi * NI + ni], af[mi], bf[ni]);
    }
}

template <int NT, int GM, int GN>
__global__ void __launch_bounds__(256, (NT == 64) ? 2 : 1) k_mma_gemm(
    const float* __restrict__ A, int lda,
    const float* __restrict__ B, int ldb,
    float* __restrict__ C, int ldc, int K,
    const float* __restrict__ bias, const float* __restrict__ scaler)
{
    constexpr int WM = 128 / GM, WN = NT / GN;
    constexpr int MI = WM / 16, NI = WN / 8;
    extern __shared__ float sm[];
    float* Abuf[2] = { sm, sm + 128 * AST };
    float* Bbuf[2] = { sm + 2 * 128 * AST, sm + 2 * 128 * AST + NT * AST };

    const int m0 = blockIdx.y * 128, n0 = blockIdx.x * NT;
    const int t = threadIdx.x, wid = t >> 5, lane = t & 31;
    const int wm0 = (wid % GM) * WM, wn0 = (wid / GM) * WN;
    const int g = lane >> 2, l4 = lane & 3;

    float acc[MI * NI][4];
    #pragma unroll
    for (int i = 0; i < MI * NI; i++)
        #pragma unroll
        for (int r = 0; r < 4; r++) acc[i][r] = 0.f;

    const int nch = K >> 5;
    load_chunk<NT>(A, B, lda, ldb, m0, n0, 0, Abuf[0], Bbuf[0], t);
    asm volatile("cp.async.wait_group 0;" ::: "memory");
    __syncthreads();

    for (int ch = 0; ch < nch; ch++) {
        const int cur = ch & 1;
        if (ch + 1 < nch)
            load_chunk<NT>(A, B, lda, ldb, m0, n0, (ch + 1) << 5, Abuf[cur ^ 1], Bbuf[cur ^ 1], t);
        compute_chunk<MI, NI>(Abuf[cur], Bbuf[cur], wm0, wn0, g, l4, acc);
        if (ch + 1 < nch) {
            asm volatile("cp.async.wait_group 0;" ::: "memory");
            __syncthreads();
        }
    }

    const float sc = scaler ? *scaler : 1.f;
    #pragma unroll
    for (int mi = 0; mi < MI; mi++) {
        const int r0 = m0 + wm0 + mi * 16 + g;
        #pragma unroll
        for (int ni = 0; ni < NI; ni++) {
            const int col = n0 + wn0 + ni * 8 + 2 * l4;
            float bx = 0.f, by = 0.f;
            if (bias) { bx = bias[col]; by = bias[col + 1]; }
            const float* a = acc[mi * NI + ni];
            float2 v0 = { (a[0] + bx) * sc, (a[1] + by) * sc };
            float2 v1 = { (a[2] + bx) * sc, (a[3] + by) * sc };
            *(float2*)&C[(long long)r0 * ldc + col] = v0;
            *(float2*)&C[(long long)(r0 + 8) * ldc + col] = v1;
        }
    }
}

// ======================================================================
// fp32 SIMT idx projections (round-14 tiling, bit-validated) with
// register prefetch: LDG for chunk k+1 issues AFTER the stores/sync
// and BEFORE the 256-FMA block, so its latency hides under compute.
// Tiling + per-element accumulation order unchanged -> bit-identical.
// ======================================================================
#define SMS 68
__global__ void k_idxproj(const float* __restrict__ hs,
                          const float* __restrict__ Wq, const float* __restrict__ Wk)
{
    __shared__ float As[16 * SMS];
    __shared__ float Bs[16 * SMS];
    const int t  = threadIdx.x;
    const int tx = t & 15, ty = t >> 4;
    const int m0 = blockIdx.y * 64;
    const int n0 = blockIdx.x * 64;
    const float* B = (n0 < 128) ? Wq : Wk;
    float* C = (n0 < 128) ? g_qI : g_kI;
    const int nb = n0 & 127;

    const int lm = t >> 2;
    const int lk = (t & 3) << 2;
    const float* Ap = hs + (size_t)(m0 + lm) * DIM_ + lk;
    const float* Bp = B + (size_t)(nb + lm) * DIM_ + lk;

    float4 av = *(const float4*)(Ap);
    float4 bv = *(const float4*)(Bp);

    float acc[4][4] = {};
    for (int k0 = 0; k0 < DIM_; k0 += 16) {
        __syncthreads();
        As[(lk+0)*SMS+lm]=av.x; As[(lk+1)*SMS+lm]=av.y;
        As[(lk+2)*SMS+lm]=av.z; As[(lk+3)*SMS+lm]=av.w;
        Bs[(lk+0)*SMS+lm]=bv.x; Bs[(lk+1)*SMS+lm]=bv.y;
        Bs[(lk+2)*SMS+lm]=bv.z; Bs[(lk+3)*SMS+lm]=bv.w;
        __syncthreads();
        if (k0 + 16 < DIM_) {   // prefetch next chunk; latency covered by FMAs
            av = *(const float4*)(Ap + k0 + 16);
            bv = *(const float4*)(Bp + k0 + 16);
        }
        #pragma unroll
        for (int kk = 0; kk < 16; kk++) {
            float4 a = *(const float4*)&As[kk*SMS + (ty<<2)];
            float4 b = *(const float4*)&Bs[kk*SMS + (tx<<2)];
            float ar[4] = {a.x,a.y,a.z,a.w};
            float br[4] = {b.x,b.y,b.z,b.w};
            #pragma unroll
            for (int i=0;i<4;i++)
                #pragma unroll
                for (int j=0;j<4;j++)
                    acc[i][j] = fmaf(ar[i], br[j], acc[i][j]);
        }
    }
    #pragma unroll
    for (int i=0;i<4;i++){
        int m = m0 + (ty<<2) + i;
        #pragma unroll
        for (int j=0;j<4;j++)
            C[(size_t)m*128 + nb + (tx<<2) + j] = acc[i][j];
    }
}

// ======================================================================
// Index scores v3.1 (validated round 14).
// ======================================================================
__global__ void __launch_bounds__(256, 2) k_idx_scores(
    const int* __restrict__ coords,
    const float* __restrict__ W1g, const float* __restrict__ b1g,
    const float* __restrict__ W2g, const float* __restrict__ b2g,
    const float* __restrict__ rpe_table)
{
    extern __shared__ float dsm[];
    float* Ks   = dsm;
    float* qrow = dsm + 128 * 128;
    float* rpes = qrow + 8 * 128;
    float* w1s  = rpes + 520;
    float* w2s  = w1s + 32;
    float* b1s  = w2s + 32;
    float* b2s  = b1s + 8;
    int*   poss = (int*)(b2s + 4);
    int*   posq = poss + 512;

    const int qb   = blockIdx.x;
    const int img  = qb >> 6;
    const int gq0  = qb * 8;
    const int base = img << 9;
    const int t = threadIdx.x;
    const int q2 = t >> 6;
    const int kk = t & 63;

    {
        int q = t >> 5, c4 = (t & 31) << 2;
        *(float4*)&qrow[q * 128 + c4] = *(const float4*)&g_qI[(size_t)(gq0 + q) * 128 + c4];
    }
    for (int i = t; i < NBUCK_ * IH_; i += 256) rpes[i] = rpe_table[i];
    if (t < 32) w1s[t] = W1g[t];
    else if (t < 64) w2s[t - 32] = W2g[t - 32];
    else if (t < 72) b1s[t - 64] = b1g[t - 64];
    else if (t < 76) b2s[t - 72] = b2g[t - 72];
    else if (t >= 128 && t < 136) posq[t - 128] = coords[(size_t)(gq0 + t - 128) * 2 + 1];
    for (int i = t; i < LI_; i += 256) poss[i] = coords[(size_t)(base + i) * 2 + 1];
    __syncthreads();

    float* outbase = g_scores + (size_t)img * LI_ * LI_;
    const int q0l = (qb & 63) * 8 + q2 * 2;
    const int posq0 = posq[q2 * 2], posq1 = posq[q2 * 2 + 1];
    const float* qr0 = qrow + (q2 * 2) * 128;
    const float* qr1 = qr0 + 128;

    for (int w = 0; w < 4; w++) {
        #pragma unroll
        for (int i = 0; i < 16; i++) {
            int fid = i * 256 + t;
            int row = fid >> 5, c4 = fid & 31;
            int c4s = c4 ^ (row & 31);
            cp_async16(smem_u32(Ks + row * 128 + c4s * 4),
                       g_kI + (size_t)(base + w * 128 + row) * 128 + c4 * 4);
        }
        asm volatile("cp.async.commit_group;" ::: "memory");
        asm volatile("cp.async.wait_group 0;" ::: "memory");
        __syncthreads();

        const float* kr0 = Ks + kk * 128;
        const float* kr1 = Ks + (kk + 64) * 128;
        const int kswz = kk & 31;

        float dot[2][2][8];
        #pragma unroll
        for (int h = 0; h < 8; h++) {
            float d00 = 0.f, d01 = 0.f, d10 = 0.f, d11 = 0.f;
            #pragma unroll
            for (int j = 0; j < 4; j++) {
                int c4 = h * 4 + j;
                float4 b0 = *(const float4*)&kr0[(c4 ^ kswz) * 4];
                float4 b1 = *(const float4*)&kr1[(c4 ^ kswz) * 4];
                float4 a0 = *(const float4*)&qr0[c4 * 4];
                float4 a1 = *(const float4*)&qr1[c4 * 4];
                d00 += a0.x*b0.x + a0.y*b0.y + a0.z*b0.z + a0.w*b0.w;
                d01 += a1.x*b0.x + a1.y*b0.y + a1.z*b0.z + a1.w*b0.w;
                d10 += a0.x*b1.x + a0.y*b1.y + a0.z*b1.z + a0.w*b1.w;
                d11 += a1.x*b1.x + a1.y*b1.y + a1.z*b1.z + a1.w*b1.w;
            }
            dot[0][0][h] = d00; dot[0][1][h] = d01;
            dot[1][0][h] = d10; dot[1][1][h] = d11;
        }

        #pragma unroll
        for (int kq = 0; kq < 2; kq++) {
            const int kglob = w * 128 + kk + kq * 64;
            const int pk = poss[kglob];
            #pragma unroll
            for (int qq = 0; qq < 2; qq++) {
                int rel = (qq ? posq1 : posq0) - pk;
                rel = rel < -64 ? -64 : (rel > 64 ? 64 : rel);
                const float* rp = &rpes[(rel + 64) * IH_];
                float xg[IH_];
                #pragma unroll
                for (int i = 0; i < IH_; i++) xg[i] = dot[kq][qq][IH_ + i] + rp[i];
                float hg[GH_];
                #pragma unroll
                for (int j = 0; j < GH_; j++) {
                    float s = b1s[j];
                    #pragma unroll
                    for (int i = 0; i < IH_; i++) s = fmaf(w1s[j * IH_ + i], xg[i], s);
                    hg[j] = fmaxf(s, 0.f);
                }
                float score = 0.f;
                #pragma unroll
                for (int i = 0; i < IH_; i++) {
                    float s = b2s[i];
                    #pragma unroll
                    for (int j = 0; j < GH_; j++) s = fmaf(w2s[i * GH_ + j], hg[j], s);
                    float gi = 1.f / (1.f + expf(-s));
                    float rs = fmaxf(dot[kq][qq][i] + rp[i], 0.f);
                    score = fmaf(rs, gi, score);
                }
                outbase[(size_t)(q0l + qq) * LI_ + kglob] = score;
            }
        }
        __syncthreads();
    }
}

// ======================================================================
// Exact top-K (validated round 8).
// ======================================================================
__global__ void __launch_bounds__(256) k_topk()
{
    int row  = blockIdx.x;
    int img  = row >> 9;
    const float* sc = g_scores + (size_t)img * LI_ * LI_ + (size_t)(row & 511) * LI_;
    __shared__ unsigned skeys[LI_];
    __shared__ unsigned hist[257];
    __shared__ unsigned mwords[16];
    __shared__ unsigned short eqidx[LI_];
    __shared__ unsigned s_prefix, s_kth, s_eqcnt;
    int t = threadIdx.x;

    for (int i = t; i < LI_; i += 256) {
        unsigned u = __float_as_uint(sc[i]);
        u = (u & 0x80000000u) ? ~u : (u | 0x80000000u);
        skeys[i] = u;
    }
    if (t == 0) { s_prefix = 0; s_kth = KSEL_; s_eqcnt = 0; }
    if (t < 16) mwords[t] = 0;
    __syncthreads();

    unsigned prefmask = 0;
    for (int r = 0; r < 4; r++) {
        int shift = 24 - 8 * r;
        hist[t] = 0;
        if (t == 0) hist[256] = 0;
        __syncthreads();
        unsigned pref = s_prefix, kth = s_kth;
        for (int i = t; i < LI_; i += 256) {
            unsigned u = skeys[i];
            if ((u & prefmask) == pref) atomicAdd(&hist[(u >> shift) & 255], 1u);
        }
        __syncthreads();
        #pragma unroll
        for (int off = 1; off < 256; off <<= 1) {
            unsigned add = (t + off < 256) ? hist[t + off] : 0u;
            __syncthreads();
            hist[t] += add;
            __syncthreads();
        }
        unsigned sfx = hist[t];
        unsigned nx  = hist[t + 1];
        if (sfx >= kth && nx < kth) {
            s_kth    = kth - nx;
            s_prefix = pref | ((unsigned)t << shift);
        }
        prefmask |= (0xFFu << shift);
        __syncthreads();
    }
    unsigned tau = s_prefix;

    for (int i = t; i < LI_; i += 256) {
        unsigned u = skeys[i];
        if (u > tau) {
            atomicOr(&mwords[i >> 5], 1u << (i & 31));
        } else if (u == tau) {
            unsigned p = atomicAdd(&s_eqcnt, 1u);
            eqidx[p] = (unsigned short)i;
        }
    }
    __syncthreads();
    if (t == 0) {
        int cg = 0;
        #pragma unroll
        for (int w = 0; w < 16; w++) cg += __popc(mwords[w]);
        int need = KSEL_ - cg;
        int ce = (int)s_eqcnt;
        if (need > 0) {
            if (ce <= need) {
                for (int j = 0; j < ce; j++) { int i = eqidx[j]; mwords[i >> 5] |= 1u << (i & 31); }
            } else {
                for (int a = 1; a < ce; a++) {
                    unsigned short v = eqidx[a]; int b = a - 1;
                    while (b >= 0 && eqidx[b] > v) { eqidx[b + 1] = eqidx[b]; b--; }
                    eqidx[b + 1] = v;
                }
                for (int j = 0; j < need; j++) { int i = eqidx[j]; mwords[i >> 5] |= 1u << (i & 31); }
            }
        }
    }
    __syncthreads();
    if (t < 16) g_selmask[(size_t)row * 16 + t] = mwords[t];
}

// ======================================================================
// Fused flash attention (validated round 14).
// ======================================================================
__global__ void __launch_bounds__(256, 2) k_flash()
{
    extern __shared__ float sm[];
    float* Qs  = sm;
    float* Ks  = Qs + 128 * 68;
    float* VTs = Ks + 64 * 68;
    unsigned* mskS = (unsigned*)(VTs + 64 * 68);

    const int qt = blockIdx.x, z = blockIdx.y;
    const int img = z >> 4, h = z & 15;
    const int t = threadIdx.x, w = t >> 5, lane = t & 31;
    const int g = lane >> 2, l4 = lane & 3;
    const int qrow0 = img * 512 + qt * 128;

    const float* Qg  = g_qkv + (size_t)qrow0 * 3072 + h * 64;
    const float* Kg0 = g_qkv + (size_t)img * 512 * 3072 + 1024 + h * 64;
    const float* VTg = g_vt + (size_t)z * (DH_ * LI_);

    #pragma unroll
    for (int i = 0; i < 8; i++) {
        int fid = t + i * 256;
        int row = fid >> 4, c4 = (fid & 15) << 2;
        cp_async16(smem_u32(Qs + row * 68 + c4), Qg + (size_t)row * 3072 + c4);
    }
    asm volatile("cp.async.commit_group;" ::: "memory");
    #pragma unroll
    for (int i = 0; i < 8; i++) {
        int widx = t + i * 256;
        mskS[widx] = g_selmask[(size_t)qrow0 * 16 + widx];
    }
    asm volatile("cp.async.wait_group 0;" ::: "memory");
    __syncthreads();

    const int rA = w * 16 + g, rB = rA + 8;

    uint32_t qf[8][4];
    #pragma unroll
    for (int kk = 0; kk < 8; kk++) {
        const float* ap = Qs + kk * 8 + l4;
        qf[kk][0] = f2tf32(ap[rA * 68]);
        qf[kk][1] = f2tf32(ap[rB * 68]);
        qf[kk][2] = f2tf32(ap[rA * 68 + 4]);
        qf[kk][3] = f2tf32(ap[rB * 68 + 4]);
    }

    float mrow0 = FNEG, mrow1 = FNEG, lrow0 = 0.f, lrow1 = 0.f;
    float oacc[8][4];
    #pragma unroll
    for (int i = 0; i < 8; i++)
        #pragma unroll
        for (int r = 0; r < 4; r++) oacc[i][r] = 0.f;

    for (int kt = 0; kt < 8; kt++) {
        const float* Kg = Kg0 + (size_t)(kt * 64) * 3072;
        #pragma unroll
        for (int i = 0; i < 4; i++) {
            int fid = t + i * 256;
            int row = fid >> 4, c4 = (fid & 15) << 2;
            cp_async16(smem_u32(Ks + row * 68 + c4), Kg + (size_t)row * 3072 + c4);
        }
        asm volatile("cp.async.commit_group;" ::: "memory");
        #pragma unroll
        for (int i = 0; i < 4; i++) {
            int fid = t + i * 256;
            int row = fid >> 4, c4 = (fid & 15) << 2;
            cp_async16(smem_u32(VTs + row * 68 + c4), VTg + (size_t)row * 512 + kt * 64 + c4);
        }
        asm volatile("cp.async.commit_group;" ::: "memory");
        asm volatile("cp.async.wait_group 1;" ::: "memory");
        __syncthreads();

        float sacc[8][4];
        #pragma unroll
        for (int i = 0; i < 8; i++)
            #pragma unroll
            for (int r = 0; r < 4; r++) sacc[i][r] = 0.f;
        #pragma unroll
        for (int kk = 0; kk < 8; kk++) {
            #pragma unroll
            for (int ni = 0; ni < 8; ni++) {
                const float* bp = Ks + (ni * 8 + g) * 68 + kk * 8 + l4;
                uint32_t bf[2] = { f2tf32(bp[0]), f2tf32(bp[4]) };
                mma8(sacc[ni], qf[kk], bf);
            }
        }

        float mx0 = FNEG, mx1 = FNEG;
        #pragma unroll
        for (int ni = 0; ni < 8; ni++) {
            int col = ni * 8 + 2 * l4;
            int wI = (kt << 1) + (col >> 5), bI = col & 31;
            unsigned mwA = mskS[rA * 16 + wI];
            unsigned mwB = mskS[rB * 16 + wI];
            float v0 = ((mwA >> bI) & 1u)       ? sacc[ni][0] * 0.125f : FNEG;
            float v1 = ((mwA >> (bI + 1)) & 1u) ? sacc[ni][1] * 0.125f : FNEG;
            float v2 = ((mwB >> bI) & 1u)       ? sacc[ni][2] * 0.125f : FNEG;
            float v3 = ((mwB >> (bI + 1)) & 1u) ? sacc[ni][3] * 0.125f : FNEG;
            sacc[ni][0] = v0; sacc[ni][1] = v1; sacc[ni][2] = v2; sacc[ni][3] = v3;
            mx0 = fmaxf(mx0, fmaxf(v0, v1));
            mx1 = fmaxf(mx1, fmaxf(v2, v3));
        }
        mx0 = fmaxf(mx0, __shfl_xor_sync(0xffffffffu, mx0, 1));
        mx0 = fmaxf(mx0, __shfl_xor_sync(0xffffffffu, mx0, 2));
        mx1 = fmaxf(mx1, __shfl_xor_sync(0xffffffffu, mx1, 1));
        mx1 = fmaxf(mx1, __shfl_xor_sync(0xffffffffu, mx1, 2));

        float mn0 = fmaxf(mrow0, mx0), mn1 = fmaxf(mrow1, mx1);
        float al0 = fast_exp(mrow0 - mn0), al1 = fast_exp(mrow1 - mn1);
        float pvd0 = (mn0 > -1e29f) ? 1.f : 0.f;
        float pvd1 = (mn1 > -1e29f) ? 1.f : 0.f;

        float ps0 = 0.f, ps1 = 0.f;
        #pragma unroll
        for (int ni = 0; ni < 8; ni++) {
            float p0 = fast_exp(sacc[ni][0] - mn0) * pvd0;
            float p1 = fast_exp(sacc[ni][1] - mn0) * pvd0;
            float p2 = fast_exp(sacc[ni][2] - mn1) * pvd1;
            float p3 = fast_exp(sacc[ni][3] - mn1) * pvd1;
            ps0 += p0 + p1; ps1 += p2 + p3;
            sacc[ni][0] = p0; sacc[ni][1] = p1; sacc[ni][2] = p2; sacc[ni][3] = p3;
        }
        ps0 += __shfl_xor_sync(0xffffffffu, ps0, 1);
        ps0 += __shfl_xor_sync(0xffffffffu, ps0, 2);
        ps1 += __shfl_xor_sync(0xffffffffu, ps1, 1);
        ps1 += __shfl_xor_sync(0xffffffffu, ps1, 2);
        lrow0 = lrow0 * al0 + ps0;
        lrow1 = lrow1 * al1 + ps1;
        mrow0 = mn0; mrow1 = mn1;
        #pragma unroll
        for (int i = 0; i < 8; i++) {
            oacc[i][0] *= al0; oacc[i][1] *= al0;
            oacc[i][2] *= al1; oacc[i][3] *= al1;
        }

        asm volatile("cp.async.wait_group 0;" ::: "memory");
        __syncthreads();

        const int src0 = (lane & ~3) | (l4 >> 1);
        const int src1 = src0 + 2;
        const bool odd = (l4 & 1);
        #pragma unroll
        for (int kk = 0; kk < 8; kk++) {
            const float* p = sacc[kk];
            float x0 = __shfl_sync(0xffffffffu, p[0], src0);
            float x1 = __shfl_sync(0xffffffffu, p[1], src0);
            float y0 = __shfl_sync(0xffffffffu, p[2], src0);
            float y1 = __shfl_sync(0xffffffffu, p[3], src0);
            float u0 = __shfl_sync(0xffffffffu, p[0], src1);
            float u1 = __shfl_sync(0xffffffffu, p[1], src1);
            float v0 = __shfl_sync(0xffffffffu, p[2], src1);
            float v1 = __shfl_sync(0xffffffffu, p[3], src1);
            uint32_t af[4] = { f2tf32(odd ? x1 : x0), f2tf32(odd ? y1 : y0),
                               f2tf32(odd ? u1 : u0), f2tf32(odd ? v1 : v0) };
            #pragma unroll
            for (int ni = 0; ni < 8; ni++) {
                const float* bp = VTs + (ni * 8 + g) * 68 + kk * 8 + l4;
                uint32_t bf[2] = { f2tf32(bp[0]), f2tf32(bp[4]) };
                mma8(oacc[ni], af, bf);
            }
        }
        __syncthreads();
    }

    const float inv0 = 1.f / lrow0, inv1 = 1.f / lrow1;
    float* OA = g_attout + (size_t)(qrow0 + rA) * DIM_ + h * 64;
    float* OB = g_attout + (size_t)(qrow0 + rB) * DIM_ + h * 64;
    #pragma unroll
    for (int ni = 0; ni < 8; ni++) {
        int col = ni * 8 + 2 * l4;
        *(float2*)&OA[col] = make_float2(oacc[ni][0] * inv0, oacc[ni][1] * inv0);
        *(float2*)&OB[col] = make_float2(oacc[ni][2] * inv1, oacc[ni][3] * inv1);
    }
}

// ======================================================================
// V transpose
// ======================================================================
__global__ void k_vt()
{
    __shared__ float s[32][65];
    const int z = blockIdx.x, kb = blockIdx.y;
    const int img = z >> 4, h = z & 15;
    const int t = threadIdx.x;
    const float* V = g_qkv + (size_t)img * LI_ * 3072 + 2048 + h * 64;
    const int kk = t >> 6, d = t & 63;
    #pragma unroll
    for (int i = 0; i < 8; i++) {
        int k = kb * 32 + kk + i * 4;
        s[kk + i * 4][d] = V[(size_t)k * 3072 + d];
    }
    __syncthreads();
    float* out = g_vt + (size_t)z * (DH_ * LI_) + kb * 32;
    const int ko = t & 31, dw = t >> 5;
    #pragma unroll
    for (int i = 0; i < 8; i++) {
        int dd = dw + i * 8;
        out[(size_t)dd * LI_ + ko] = s[ko][dd];
    }
}

// ======================================================================
// RoPE
// ======================================================================
__global__ void k_rope(const float* __restrict__ rope)
{
    __shared__ float cs[32], sns[32];
    int s = blockIdx.x;
    int t = threadIdx.x;
    if (t < 32) {
        float ang = rope[(size_t)s * 32 + t];
        cs[t] = cosf(ang);
        sns[t] = sinf(ang);
    }
    __syncthreads();
    int h = t >> 5, d = t & 31;
    float c = cs[d], sn = sns[d];
    float* q = g_qkv + (size_t)s * 3072 + h * 64;
    float* k = q + 1024;
    float q1 = q[d], q2 = q[d + 32];
    q[d]      = q1 * c - q2 * sn;
    q[d + 32] = q2 * c + q1 * sn;
    float k1 = k[d], k2 = k[d + 32];
    k[d]      = k1 * c - k2 * sn;
    k[d + 32] = k2 * c + k1 * sn;
}

// ======================================================================
// Launch: parallel chains. Code order: launch #4 = k_idxproj (ncu slot).
// ======================================================================
extern "C" void kernel_launch(void* const* d_in, const int* in_sizes, int n_in,
                              void* d_out, int out_size)
{
    const float* hs     = (const float*)d_in[0];
    const int*   coords = (const int*)  d_in[1];
    const float* rope   = (const float*)d_in[3];
    const float* Wq_idx = (const float*)d_in[4];
    const float* Wk_idx = (const float*)d_in[5];
    const float* W1g    = (const float*)d_in[6];
    const float* b1g    = (const float*)d_in[7];
    const float* W2g    = (const float*)d_in[8];
    const float* b2g    = (const float*)d_in[9];
    const float* rpe    = (const float*)d_in[10];
    const float* Wqkv_d = (const float*)d_in[11];
    const float* bqkv_d = (const float*)d_in[12];
    const float* Wqkv_u = (const float*)d_in[13];
    const float* bqkv_u = (const float*)d_in[14];
    const float* Wp_d   = (const float*)d_in[15];
    const float* bp_d   = (const float*)d_in[16];
    const float* Wp_u   = (const float*)d_in[17];
    const float* bp_u   = (const float*)d_in[18];
    const float* scaler = (const float*)d_in[19];
    float* out = (float*)d_out;

    float *tmp1, *qkv, *attout, *tmp2;
    cudaGetSymbolAddress((void**)&tmp1,   g_tmp1);
    cudaGetSymbolAddress((void**)&qkv,    g_qkv);
    cudaGetSymbolAddress((void**)&attout, g_attout);
    cudaGetSymbolAddress((void**)&tmp2,   g_tmp2);

    const int dyn64  = (2 * 128 + 2 * 64)  * AST * 4;
    const int dynFl  = (128 * 68 + 64 * 68 + 64 * 68) * 4 + 128 * 16 * 4;
    const int dynIS  = (128 * 128 + 8 * 128 + 520 + 32 + 32 + 8 + 4) * 4 + 512 * 4 + 8 * 4;
    cudaFuncSetAttribute((const void*)k_mma_gemm<64,4,2>,  cudaFuncAttributeMaxDynamicSharedMemorySize, dyn64);
    cudaFuncSetAttribute((const void*)k_flash, cudaFuncAttributeMaxDynamicSharedMemorySize, dynFl);
    cudaFuncSetAttribute((const void*)k_idx_scores, cudaFuncAttributeMaxDynamicSharedMemorySize, dynIS);

    static cudaStream_t sB = [](){
        cudaStream_t s; cudaStreamCreateWithFlags(&s, cudaStreamNonBlocking); return s;
    }();
    static cudaEvent_t eFork = [](){
        cudaEvent_t e; cudaEventCreateWithFlags(&e, cudaEventDisableTiming); return e;
    }();
    static cudaEvent_t eJoin = [](){
        cudaEvent_t e; cudaEventCreateWithFlags(&e, cudaEventDisableTiming); return e;
    }();

    cudaEventRecord(eFork, 0);
    cudaStreamWaitEvent(sB, eFork, 0);

    // (1-3) chain B
    k_mma_gemm<64,4,2><<<dim3(4, 16), 256, dyn64, sB>>>(
        hs, DIM_, Wqkv_d, DIM_, tmp1, BOT_, DIM_, bqkv_d, nullptr);
    k_mma_gemm<64,4,2><<<dim3(48, 16), 256, dyn64, sB>>>(
        tmp1, BOT_, Wqkv_u, BOT_, qkv, 3 * DIM_, BOT_, bqkv_u, nullptr);
    k_vt<<<dim3(NIMG_ * H_, 16), 256, 0, sB>>>();
    // (4) chain A: idx projections (R14 tiling + prefetch)  <-- ncu slot
    k_idxproj<<<dim3(4, 32), 256>>>(hs, Wq_idx, Wk_idx);
    // (5) chain B
    k_rope<<<S_, 512, 0, sB>>>(rope);
    // (6-7) chain A
    k_idx_scores<<<256, 256, dynIS>>>(coords, W1g, b1g, W2g, b2g, rpe);
    k_topk<<<S_, 256>>>();

    cudaEventRecord(eJoin, sB);
    cudaStreamWaitEvent(0, eJoin, 0);

    // flash
    k_flash<<<dim3(4, NIMG_ * H_), 256, dynFl>>>();

    // final projections
    k_mma_gemm<64,4,2><<<dim3(4, 16), 256, dyn64>>>(
        attout, DIM_, Wp_d, DIM_, tmp2, BOT_, DIM_, bp_d, nullptr);
    k_mma_gemm<64,4,2><<<dim3(16, 16), 256, dyn64>>>(
        tmp2, BOT_, Wp_u, BOT_, out, DIM_, BOT_, bp_u, scaler);
}

// round 17
// speedup vs baseline: 1.0837x; 1.0058x over previous
#include <cuda_runtime.h>
#include <math.h>
#include <stdint.h>

// ---------------- problem constants ----------------
#define S_    2048
#define NIMG_ 4
#define LI_   512
#define H_    16
#define DH_   64
#define DIM_  1024
#define BOT_  256
#define KSEL_ 256
#define IH_   4
#define ID_   16
#define GH_   8
#define NBUCK_ 129
#define FNEG  -1e30f

// ---------------- scratch (device globals; no runtime alloc) ----------------
__device__ float    g_tmp1[S_ * BOT_];
__device__ float    g_qkv [S_ * 3 * DIM_];
__device__ float    g_vt  [NIMG_ * H_ * DH_ * LI_];
__device__ float    g_qI  [S_ * 128];
__device__ float    g_kI  [S_ * 128];
__device__ float    g_scores[NIMG_ * LI_ * LI_];
__device__ unsigned g_selmask[S_ * 16];
__device__ float    g_attout[S_ * DIM_];
__device__ float    g_tmp2[S_ * BOT_];
__device__ float    g_dump[128 * DIM_];   // sink for the 1-block profiling launch

// ---------------- helpers ----------------
__device__ __forceinline__ uint32_t smem_u32(const void* p) {
    uint32_t a;
    asm("{ .reg .u64 t; cvta.to.shared.u64 t, %1; cvt.u32.u64 %0, t; }" : "=r"(a) : "l"(p));
    return a;
}
__device__ __forceinline__ void cp_async16(uint32_t sa, const void* gp) {
    asm volatile("cp.async.cg.shared.global [%0], [%1], 16;" :: "r"(sa), "l"(gp) : "memory");
}
__device__ __forceinline__ uint32_t f2tf32(float v) {
    uint32_t u;
    asm("cvt.rna.tf32.f32 %0, %1;" : "=r"(u) : "f"(v));
    return u;
}
__device__ __forceinline__ void mma8(float* c, const uint32_t* a, const uint32_t* b) {
    asm volatile("mma.sync.aligned.m16n8k8.row.col.f32.tf32.tf32.f32 "
        "{%0,%1,%2,%3}, {%4,%5,%6,%7}, {%8,%9}, {%0,%1,%2,%3};"
        : "+f"(c[0]), "+f"(c[1]), "+f"(c[2]), "+f"(c[3])
        : "r"(a[0]), "r"(a[1]), "r"(a[2]), "r"(a[3]), "r"(b[0]), "r"(b[1]));
}

// FMA-pipe exp for x <= 0 (softmax value path). fast_exp(0) == 1.0f exactly.
__device__ __forceinline__ float fast_exp(float x) {
    x = fmaxf(x, -88.0f);
    float y = x * 1.44269504088896341f;
    float r = rintf(y);
    float f = y - r;
    float p = 1.53386867e-4f;
    p = fmaf(p, f, 1.33938769e-3f);
    p = fmaf(p, f, 9.61833251e-3f);
    p = fmaf(p, f, 5.55036329e-2f);
    p = fmaf(p, f, 2.40226452e-1f);
    p = fmaf(p, f, 6.93147182e-1f);
    p = fmaf(p, f, 1.0f);
    int ir = (int)r;
    float s = __int_as_float((ir + 127) << 23);
    return p * s;
}

// ======================================================================
// tf32 mma.sync GEMM (TN), NT=64 high-occupancy tile (validated R12).
// ======================================================================
#define AST 36

template<int NT>
__device__ __forceinline__ void load_chunk(
    const float* __restrict__ A, const float* __restrict__ B,
    int lda, int ldb, int m0, int n0, int k0,
    float* __restrict__ Abuf, float* __restrict__ Bbuf, int t)
{
    const int arow = t >> 3, ac4 = (t & 7) << 2;
    #pragma unroll
    for (int i = 0; i < 4; i++) {
        int row = arow + i * 32;
        cp_async16(smem_u32(Abuf + row * AST + ac4),
                   A + (long long)(m0 + row) * lda + k0 + ac4);
    }
    #pragma unroll
    for (int i = 0; i < NT / 32; i++) {
        int row = arow + i * 32;
        cp_async16(smem_u32(Bbuf + row * AST + ac4),
                   B + (long long)(n0 + row) * ldb + k0 + ac4);
    }
    asm volatile("cp.async.commit_group;" ::: "memory");
}

template<int MI, int NI>
__device__ __forceinline__ void compute_chunk(
    const float* __restrict__ Abuf, const float* __restrict__ Bbuf,
    int wm0, int wn0, int g, int l4, float (*acc)[4])
{
    #pragma unroll
    for (int ks = 0; ks < 4; ks++) {
        const int kk = ks * 8;
        uint32_t af[MI][4], bf[NI][2];
        #pragma unroll
        for (int mi = 0; mi < MI; mi++) {
            const float* p = Abuf + (wm0 + mi * 16 + g) * AST + kk + l4;
            af[mi][0] = f2tf32(p[0]);
            af[mi][2] = f2tf32(p[4]);
            af[mi][1] = f2tf32(p[8 * AST]);
            af[mi][3] = f2tf32(p[8 * AST + 4]);
        }
        #pragma unroll
        for (int ni = 0; ni < NI; ni++) {
            const float* p = Bbuf + (wn0 + ni * 8 + g) * AST + kk + l4;
            bf[ni][0] = f2tf32(p[0]);
            bf[ni][1] = f2tf32(p[4]);
        }
        #pragma unroll
        for (int mi = 0; mi < MI; mi++)
            #pragma unroll
            for (int ni = 0; ni < NI; ni++)
                mma8(acc[mi * NI + ni], af[mi], bf[ni]);
    }
}

template <int NT, int GM, int GN>
__global__ void __launch_bounds__(256, (NT == 64) ? 2 : 1) k_mma_gemm(
    const float* __restrict__ A, int lda,
    const float* __restrict__ B, int ldb,
    float* __restrict__ C, int ldc, int K,
    const float* __restrict__ bias, const float* __restrict__ scaler)
{
    constexpr int WM = 128 / GM, WN = NT / GN;
    constexpr int MI = WM / 16, NI = WN / 8;
    extern __shared__ float sm[];
    float* Abuf[2] = { sm, sm + 128 * AST };
    float* Bbuf[2] = { sm + 2 * 128 * AST, sm + 2 * 128 * AST + NT * AST };

    const int m0 = blockIdx.y * 128, n0 = blockIdx.x * NT;
    const int t = threadIdx.x, wid = t >> 5, lane = t & 31;
    const int wm0 = (wid % GM) * WM, wn0 = (wid / GM) * WN;
    const int g = lane >> 2, l4 = lane & 3;

    float acc[MI * NI][4];
    #pragma unroll
    for (int i = 0; i < MI * NI; i++)
        #pragma unroll
        for (int r = 0; r < 4; r++) acc[i][r] = 0.f;

    const int nch = K >> 5;
    load_chunk<NT>(A, B, lda, ldb, m0, n0, 0, Abuf[0], Bbuf[0], t);
    asm volatile("cp.async.wait_group 0;" ::: "memory");
    __syncthreads();

    for (int ch = 0; ch < nch; ch++) {
        const int cur = ch & 1;
        if (ch + 1 < nch)
            load_chunk<NT>(A, B, lda, ldb, m0, n0, (ch + 1) << 5, Abuf[cur ^ 1], Bbuf[cur ^ 1], t);
        compute_chunk<MI, NI>(Abuf[cur], Bbuf[cur], wm0, wn0, g, l4, acc);
        if (ch + 1 < nch) {
            asm volatile("cp.async.wait_group 0;" ::: "memory");
            __syncthreads();
        }
    }

    const float sc = scaler ? *scaler : 1.f;
    #pragma unroll
    for (int mi = 0; mi < MI; mi++) {
        const int r0 = m0 + wm0 + mi * 16 + g;
        #pragma unroll
        for (int ni = 0; ni < NI; ni++) {
            const int col = n0 + wn0 + ni * 8 + 2 * l4;
            float bx = 0.f, by = 0.f;
            if (bias) { bx = bias[col]; by = bias[col + 1]; }
            const float* a = acc[mi * NI + ni];
            float2 v0 = { (a[0] + bx) * sc, (a[1] + by) * sc };
            float2 v1 = { (a[2] + bx) * sc, (a[3] + by) * sc };
            *(float2*)&C[(long long)r0 * ldc + col] = v0;
            *(float2*)&C[(long long)(r0 + 8) * ldc + col] = v1;
        }
    }
}

// ======================================================================
// fp32 SIMT idx projections (validated R16: prefetch, bit-identical).
// ======================================================================
#define SMS 68
__global__ void k_idxproj(const float* __restrict__ hs,
                          const float* __restrict__ Wq, const float* __restrict__ Wk)
{
    __shared__ float As[16 * SMS];
    __shared__ float Bs[16 * SMS];
    const int t  = threadIdx.x;
    const int tx = t & 15, ty = t >> 4;
    const int m0 = blockIdx.y * 64;
    const int n0 = blockIdx.x * 64;
    const float* B = (n0 < 128) ? Wq : Wk;
    float* C = (n0 < 128) ? g_qI : g_kI;
    const int nb = n0 & 127;

    const int lm = t >> 2;
    const int lk = (t & 3) << 2;
    const float* Ap = hs + (size_t)(m0 + lm) * DIM_ + lk;
    const float* Bp = B + (size_t)(nb + lm) * DIM_ + lk;

    float4 av = *(const float4*)(Ap);
    float4 bv = *(const float4*)(Bp);

    float acc[4][4] = {};
    for (int k0 = 0; k0 < DIM_; k0 += 16) {
        __syncthreads();
        As[(lk+0)*SMS+lm]=av.x; As[(lk+1)*SMS+lm]=av.y;
        As[(lk+2)*SMS+lm]=av.z; As[(lk+3)*SMS+lm]=av.w;
        Bs[(lk+0)*SMS+lm]=bv.x; Bs[(lk+1)*SMS+lm]=bv.y;
        Bs[(lk+2)*SMS+lm]=bv.z; Bs[(lk+3)*SMS+lm]=bv.w;
        __syncthreads();
        if (k0 + 16 < DIM_) {
            av = *(const float4*)(Ap + k0 + 16);
            bv = *(const float4*)(Bp + k0 + 16);
        }
        #pragma unroll
        for (int kk = 0; kk < 16; kk++) {
            float4 a = *(const float4*)&As[kk*SMS + (ty<<2)];
            float4 b = *(const float4*)&Bs[kk*SMS + (tx<<2)];
            float ar[4] = {a.x,a.y,a.z,a.w};
            float br[4] = {b.x,b.y,b.z,b.w};
            #pragma unroll
            for (int i=0;i<4;i++)
                #pragma unroll
                for (int j=0;j<4;j++)
                    acc[i][j] = fmaf(ar[i], br[j], acc[i][j]);
        }
    }
    #pragma unroll
    for (int i=0;i<4;i++){
        int m = m0 + (ty<<2) + i;
        #pragma unroll
        for (int j=0;j<4;j++)
            C[(size_t)m*128 + nb + (tx<<2) + j] = acc[i][j];
    }
}

// ======================================================================
// Index scores v3.1 (validated round 14).
// ======================================================================
__global__ void __launch_bounds__(256, 2) k_idx_scores(
    const int* __restrict__ coords,
    const float* __restrict__ W1g, const float* __restrict__ b1g,
    const float* __restrict__ W2g, const float* __restrict__ b2g,
    const float* __restrict__ rpe_table)
{
    extern __shared__ float dsm[];
    float* Ks   = dsm;
    float* qrow = dsm + 128 * 128;
    float* rpes = qrow + 8 * 128;
    float* w1s  = rpes + 520;
    float* w2s  = w1s + 32;
    float* b1s  = w2s + 32;
    float* b2s  = b1s + 8;
    int*   poss = (int*)(b2s + 4);
    int*   posq = poss + 512;

    const int qb   = blockIdx.x;
    const int img  = qb >> 6;
    const int gq0  = qb * 8;
    const int base = img << 9;
    const int t = threadIdx.x;
    const int q2 = t >> 6;
    const int kk = t & 63;

    {
        int q = t >> 5, c4 = (t & 31) << 2;
        *(float4*)&qrow[q * 128 + c4] = *(const float4*)&g_qI[(size_t)(gq0 + q) * 128 + c4];
    }
    for (int i = t; i < NBUCK_ * IH_; i += 256) rpes[i] = rpe_table[i];
    if (t < 32) w1s[t] = W1g[t];
    else if (t < 64) w2s[t - 32] = W2g[t - 32];
    else if (t < 72) b1s[t - 64] = b1g[t - 64];
    else if (t < 76) b2s[t - 72] = b2g[t - 72];
    else if (t >= 128 && t < 136) posq[t - 128] = coords[(size_t)(gq0 + t - 128) * 2 + 1];
    for (int i = t; i < LI_; i += 256) poss[i] = coords[(size_t)(base + i) * 2 + 1];
    __syncthreads();

    float* outbase = g_scores + (size_t)img * LI_ * LI_;
    const int q0l = (qb & 63) * 8 + q2 * 2;
    const int posq0 = posq[q2 * 2], posq1 = posq[q2 * 2 + 1];
    const float* qr0 = qrow + (q2 * 2) * 128;
    const float* qr1 = qr0 + 128;

    for (int w = 0; w < 4; w++) {
        #pragma unroll
        for (int i = 0; i < 16; i++) {
            int fid = i * 256 + t;
            int row = fid >> 5, c4 = fid & 31;
            int c4s = c4 ^ (row & 31);
            cp_async16(smem_u32(Ks + row * 128 + c4s * 4),
                       g_kI + (size_t)(base + w * 128 + row) * 128 + c4 * 4);
        }
        asm volatile("cp.async.commit_group;" ::: "memory");
        asm volatile("cp.async.wait_group 0;" ::: "memory");
        __syncthreads();

        const float* kr0 = Ks + kk * 128;
        const float* kr1 = Ks + (kk + 64) * 128;
        const int kswz = kk & 31;

        float dot[2][2][8];
        #pragma unroll
        for (int h = 0; h < 8; h++) {
            float d00 = 0.f, d01 = 0.f, d10 = 0.f, d11 = 0.f;
            #pragma unroll
            for (int j = 0; j < 4; j++) {
                int c4 = h * 4 + j;
                float4 b0 = *(const float4*)&kr0[(c4 ^ kswz) * 4];
                float4 b1 = *(const float4*)&kr1[(c4 ^ kswz) * 4];
                float4 a0 = *(const float4*)&qr0[c4 * 4];
                float4 a1 = *(const float4*)&qr1[c4 * 4];
                d00 += a0.x*b0.x + a0.y*b0.y + a0.z*b0.z + a0.w*b0.w;
                d01 += a1.x*b0.x + a1.y*b0.y + a1.z*b0.z + a1.w*b0.w;
                d10 += a0.x*b1.x + a0.y*b1.y + a0.z*b1.z + a0.w*b1.w;
                d11 += a1.x*b1.x + a1.y*b1.y + a1.z*b1.z + a1.w*b1.w;
            }
            dot[0][0][h] = d00; dot[0][1][h] = d01;
            dot[1][0][h] = d10; dot[1][1][h] = d11;
        }

        #pragma unroll
        for (int kq = 0; kq < 2; kq++) {
            const int kglob = w * 128 + kk + kq * 64;
            const int pk = poss[kglob];
            #pragma unroll
            for (int qq = 0; qq < 2; qq++) {
                int rel = (qq ? posq1 : posq0) - pk;
                rel = rel < -64 ? -64 : (rel > 64 ? 64 : rel);
                const float* rp = &rpes[(rel + 64) * IH_];
                float xg[IH_];
                #pragma unroll
                for (int i = 0; i < IH_; i++) xg[i] = dot[kq][qq][IH_ + i] + rp[i];
                float hg[GH_];
                #pragma unroll
                for (int j = 0; j < GH_; j++) {
                    float s = b1s[j];
                    #pragma unroll
                    for (int i = 0; i < IH_; i++) s = fmaf(w1s[j * IH_ + i], xg[i], s);
                    hg[j] = fmaxf(s, 0.f);
                }
                float score = 0.f;
                #pragma unroll
                for (int i = 0; i < IH_; i++) {
                    float s = b2s[i];
                    #pragma unroll
                    for (int j = 0; j < GH_; j++) s = fmaf(w2s[i * GH_ + j], hg[j], s);
                    float gi = 1.f / (1.f + expf(-s));
                    float rs = fmaxf(dot[kq][qq][i] + rp[i], 0.f);
                    score = fmaf(rs, gi, score);
                }
                outbase[(size_t)(q0l + qq) * LI_ + kglob] = score;
            }
        }
        __syncthreads();
    }
}

// ======================================================================
// Exact top-K (validated round 8).
// ======================================================================
__global__ void __launch_bounds__(256) k_topk()
{
    int row  = blockIdx.x;
    int img  = row >> 9;
    const float* sc = g_scores + (size_t)img * LI_ * LI_ + (size_t)(row & 511) * LI_;
    __shared__ unsigned skeys[LI_];
    __shared__ unsigned hist[257];
    __shared__ unsigned mwords[16];
    __shared__ unsigned short eqidx[LI_];
    __shared__ unsigned s_prefix, s_kth, s_eqcnt;
    int t = threadIdx.x;

    for (int i = t; i < LI_; i += 256) {
        unsigned u = __float_as_uint(sc[i]);
        u = (u & 0x80000000u) ? ~u : (u | 0x80000000u);
        skeys[i] = u;
    }
    if (t == 0) { s_prefix = 0; s_kth = KSEL_; s_eqcnt = 0; }
    if (t < 16) mwords[t] = 0;
    __syncthreads();

    unsigned prefmask = 0;
    for (int r = 0; r < 4; r++) {
        int shift = 24 - 8 * r;
        hist[t] = 0;
        if (t == 0) hist[256] = 0;
        __syncthreads();
        unsigned pref = s_prefix, kth = s_kth;
        for (int i = t; i < LI_; i += 256) {
            unsigned u = skeys[i];
            if ((u & prefmask) == pref) atomicAdd(&hist[(u >> shift) & 255], 1u);
        }
        __syncthreads();
        #pragma unroll
        for (int off = 1; off < 256; off <<= 1) {
            unsigned add = (t + off < 256) ? hist[t + off] : 0u;
            __syncthreads();
            hist[t] += add;
            __syncthreads();
        }
        unsigned sfx = hist[t];
        unsigned nx  = hist[t + 1];
        if (sfx >= kth && nx < kth) {
            s_kth    = kth - nx;
            s_prefix = pref | ((unsigned)t << shift);
        }
        prefmask |= (0xFFu << shift);
        __syncthreads();
    }
    unsigned tau = s_prefix;

    for (int i = t; i < LI_; i += 256) {
        unsigned u = skeys[i];
        if (u > tau) {
            atomicOr(&mwords[i >> 5], 1u << (i & 31));
        } else if (u == tau) {
            unsigned p = atomicAdd(&s_eqcnt, 1u);
            eqidx[p] = (unsigned short)i;
        }
    }
    __syncthreads();
    if (t == 0) {
        int cg = 0;
        #pragma unroll
        for (int w = 0; w < 16; w++) cg += __popc(mwords[w]);
        int need = KSEL_ - cg;
        int ce = (int)s_eqcnt;
        if (need > 0) {
            if (ce <= need) {
                for (int j = 0; j < ce; j++) { int i = eqidx[j]; mwords[i >> 5] |= 1u << (i & 31); }
            } else {
                for (int a = 1; a < ce; a++) {
                    unsigned short v = eqidx[a]; int b = a - 1;
                    while (b >= 0 && eqidx[b] > v) { eqidx[b + 1] = eqidx[b]; b--; }
                    eqidx[b + 1] = v;
                }
                for (int j = 0; j < need; j++) { int i = eqidx[j]; mwords[i >> 5] |= 1u << (i & 31); }
            }
        }
    }
    __syncthreads();
    if (t < 16) g_selmask[(size_t)row * 16 + t] = mwords[t];
}

// ======================================================================
// Fused flash attention. K/V tiles pre-converted to tf32 bits in SMEM
// (bit-identical operands; removes 8x redundant cvt in the mma loops).
// Parameterized output so a 1-block profiling launch can target g_dump.
// ======================================================================
__global__ void __launch_bounds__(256, 2) k_flash(float* __restrict__ outp)
{
    extern __shared__ float sm[];
    float* Qs  = sm;
    float* Ks  = Qs + 128 * 68;
    float* VTs = Ks + 64 * 68;
    unsigned* mskS = (unsigned*)(VTs + 64 * 68);

    const int qt = blockIdx.x, z = blockIdx.y;
    const int img = z >> 4, h = z & 15;
    const int t = threadIdx.x, w = t >> 5, lane = t & 31;
    const int g = lane >> 2, l4 = lane & 3;
    const int qrow0 = img * 512 + qt * 128;

    const float* Qg  = g_qkv + (size_t)qrow0 * 3072 + h * 64;
    const float* Kg0 = g_qkv + (size_t)img * 512 * 3072 + 1024 + h * 64;
    const float* VTg = g_vt + (size_t)z * (DH_ * LI_);

    #pragma unroll
    for (int i = 0; i < 8; i++) {
        int fid = t + i * 256;
        int row = fid >> 4, c4 = (fid & 15) << 2;
        cp_async16(smem_u32(Qs + row * 68 + c4), Qg + (size_t)row * 3072 + c4);
    }
    asm volatile("cp.async.commit_group;" ::: "memory");
    #pragma unroll
    for (int i = 0; i < 8; i++) {
        int widx = t + i * 256;
        mskS[widx] = g_selmask[(size_t)qrow0 * 16 + widx];
    }
    asm volatile("cp.async.wait_group 0;" ::: "memory");
    __syncthreads();

    const int rA = w * 16 + g, rB = rA + 8;

    uint32_t qf[8][4];
    #pragma unroll
    for (int kk = 0; kk < 8; kk++) {
        const float* ap = Qs + kk * 8 + l4;
        qf[kk][0] = f2tf32(ap[rA * 68]);
        qf[kk][1] = f2tf32(ap[rB * 68]);
        qf[kk][2] = f2tf32(ap[rA * 68 + 4]);
        qf[kk][3] = f2tf32(ap[rB * 68 + 4]);
    }

    float mrow0 = FNEG, mrow1 = FNEG, lrow0 = 0.f, lrow1 = 0.f;
    float oacc[8][4];
    #pragma unroll
    for (int i = 0; i < 8; i++)
        #pragma unroll
        for (int r = 0; r < 4; r++) oacc[i][r] = 0.f;

    for (int kt = 0; kt < 8; kt++) {
        const float* Kg = Kg0 + (size_t)(kt * 64) * 3072;
        #pragma unroll
        for (int i = 0; i < 4; i++) {
            int fid = t + i * 256;
            int row = fid >> 4, c4 = (fid & 15) << 2;
            cp_async16(smem_u32(Ks + row * 68 + c4), Kg + (size_t)row * 3072 + c4);
        }
        asm volatile("cp.async.commit_group;" ::: "memory");
        #pragma unroll
        for (int i = 0; i < 4; i++) {
            int fid = t + i * 256;
            int row = fid >> 4, c4 = (fid & 15) << 2;
            cp_async16(smem_u32(VTs + row * 68 + c4), VTg + (size_t)row * 512 + kt * 64 + c4);
        }
        asm volatile("cp.async.commit_group;" ::: "memory");
        asm volatile("cp.async.wait_group 1;" ::: "memory");  // K ready
        __syncthreads();

        // pre-convert K tile to tf32 bits (4 float4 per thread)
        #pragma unroll
        for (int i = 0; i < 4; i++) {
            int idx = i * 256 + t;
            float* p = Ks + (idx >> 4) * 68 + ((idx & 15) << 2);
            float4 v = *(float4*)p;
            v.x = __uint_as_float(f2tf32(v.x));
            v.y = __uint_as_float(f2tf32(v.y));
            v.z = __uint_as_float(f2tf32(v.z));
            v.w = __uint_as_float(f2tf32(v.w));
            *(float4*)p = v;
        }
        __syncthreads();

        float sacc[8][4];
        #pragma unroll
        for (int i = 0; i < 8; i++)
            #pragma unroll
            for (int r = 0; r < 4; r++) sacc[i][r] = 0.f;
        #pragma unroll
        for (int kk = 0; kk < 8; kk++) {
            #pragma unroll
            for (int ni = 0; ni < 8; ni++) {
                const float* bp = Ks + (ni * 8 + g) * 68 + kk * 8 + l4;
                uint32_t bf[2] = { __float_as_uint(bp[0]), __float_as_uint(bp[4]) };
                mma8(sacc[ni], qf[kk], bf);
            }
        }

        float mx0 = FNEG, mx1 = FNEG;
        #pragma unroll
        for (int ni = 0; ni < 8; ni++) {
            int col = ni * 8 + 2 * l4;
            int wI = (kt << 1) + (col >> 5), bI = col & 31;
            unsigned mwA = mskS[rA * 16 + wI];
            unsigned mwB = mskS[rB * 16 + wI];
            float v0 = ((mwA >> bI) & 1u)       ? sacc[ni][0] * 0.125f : FNEG;
            float v1 = ((mwA >> (bI + 1)) & 1u) ? sacc[ni][1] * 0.125f : FNEG;
            float v2 = ((mwB >> bI) & 1u)       ? sacc[ni][2] * 0.125f : FNEG;
            float v3 = ((mwB >> (bI + 1)) & 1u) ? sacc[ni][3] * 0.125f : FNEG;
            sacc[ni][0] = v0; sacc[ni][1] = v1; sacc[ni][2] = v2; sacc[ni][3] = v3;
            mx0 = fmaxf(mx0, fmaxf(v0, v1));
            mx1 = fmaxf(mx1, fmaxf(v2, v3));
        }
        mx0 = fmaxf(mx0, __shfl_xor_sync(0xffffffffu, mx0, 1));
        mx0 = fmaxf(mx0, __shfl_xor_sync(0xffffffffu, mx0, 2));
        mx1 = fmaxf(mx1, __shfl_xor_sync(0xffffffffu, mx1, 1));
        mx1 = fmaxf(mx1, __shfl_xor_sync(0xffffffffu, mx1, 2));

        float mn0 = fmaxf(mrow0, mx0), mn1 = fmaxf(mrow1, mx1);
        float al0 = fast_exp(mrow0 - mn0), al1 = fast_exp(mrow1 - mn1);
        float pvd0 = (mn0 > -1e29f) ? 1.f : 0.f;
        float pvd1 = (mn1 > -1e29f) ? 1.f : 0.f;

        float ps0 = 0.f, ps1 = 0.f;
        #pragma unroll
        for (int ni = 0; ni < 8; ni++) {
            float p0 = fast_exp(sacc[ni][0] - mn0) * pvd0;
            float p1 = fast_exp(sacc[ni][1] - mn0) * pvd0;
            float p2 = fast_exp(sacc[ni][2] - mn1) * pvd1;
            float p3 = fast_exp(sacc[ni][3] - mn1) * pvd1;
            ps0 += p0 + p1; ps1 += p2 + p3;
            sacc[ni][0] = p0; sacc[ni][1] = p1; sacc[ni][2] = p2; sacc[ni][3] = p3;
        }
        ps0 += __shfl_xor_sync(0xffffffffu, ps0, 1);
        ps0 += __shfl_xor_sync(0xffffffffu, ps0, 2);
        ps1 += __shfl_xor_sync(0xffffffffu, ps1, 1);
        ps1 += __shfl_xor_sync(0xffffffffu, ps1, 2);
        lrow0 = lrow0 * al0 + ps0;
        lrow1 = lrow1 * al1 + ps1;
        mrow0 = mn0; mrow1 = mn1;
        #pragma unroll
        for (int i = 0; i < 8; i++) {
            oacc[i][0] *= al0; oacc[i][1] *= al0;
            oacc[i][2] *= al1; oacc[i][3] *= al1;
        }

        asm volatile("cp.async.wait_group 0;" ::: "memory");  // V ready
        __syncthreads();

        // pre-convert V tile to tf32 bits
        #pragma unroll
        for (int i = 0; i < 4; i++) {
            int idx = i * 256 + t;
            float* p = VTs + (idx >> 4) * 68 + ((idx & 15) << 2);
            float4 v = *(float4*)p;
            v.x = __uint_as_float(f2tf32(v.x));
            v.y = __uint_as_float(f2tf32(v.y));
            v.z = __uint_as_float(f2tf32(v.z));
            v.w = __uint_as_float(f2tf32(v.w));
            *(float4*)p = v;
        }
        __syncthreads();

        const int src0 = (lane & ~3) | (l4 >> 1);
        const int src1 = src0 + 2;
        const bool odd = (l4 & 1);
        #pragma unroll
        for (int kk = 0; kk < 8; kk++) {
            const float* p = sacc[kk];
            float x0 = __shfl_sync(0xffffffffu, p[0], src0);
            float x1 = __shfl_sync(0xffffffffu, p[1], src0);
            float y0 = __shfl_sync(0xffffffffu, p[2], src0);
            float y1 = __shfl_sync(0xffffffffu, p[3], src0);
            float u0 = __shfl_sync(0xffffffffu, p[0], src1);
            float u1 = __shfl_sync(0xffffffffu, p[1], src1);
            float v0 = __shfl_sync(0xffffffffu, p[2], src1);
            float v1 = __shfl_sync(0xffffffffu, p[3], src1);
            uint32_t af[4] = { f2tf32(odd ? x1 : x0), f2tf32(odd ? y1 : y0),
                               f2tf32(odd ? u1 : u0), f2tf32(odd ? v1 : v0) };
            #pragma unroll
            for (int ni = 0; ni < 8; ni++) {
                const float* bp = VTs + (ni * 8 + g) * 68 + kk * 8 + l4;
                uint32_t bf[2] = { __float_as_uint(bp[0]), __float_as_uint(bp[4]) };
                mma8(oacc[ni], af, bf);
            }
        }
        __syncthreads();
    }

    const float inv0 = 1.f / lrow0, inv1 = 1.f / lrow1;
    float* OA = outp + (size_t)(qrow0 + rA) * DIM_ + h * 64;
    float* OB = outp + (size_t)(qrow0 + rB) * DIM_ + h * 64;
    #pragma unroll
    for (int ni = 0; ni < 8; ni++) {
        int col = ni * 8 + 2 * l4;
        *(float2*)&OA[col] = make_float2(oacc[ni][0] * inv0, oacc[ni][1] * inv0);
        *(float2*)&OB[col] = make_float2(oacc[ni][2] * inv1, oacc[ni][3] * inv1);
    }
}

// ======================================================================
// V transpose
// ======================================================================
__global__ void k_vt()
{
    __shared__ float s[32][65];
    const int z = blockIdx.x, kb = blockIdx.y;
    const int img = z >> 4, h = z & 15;
    const int t = threadIdx.x;
    const float* V = g_qkv + (size_t)img * LI_ * 3072 + 2048 + h * 64;
    const int kk = t >> 6, d = t & 63;
    #pragma unroll
    for (int i = 0; i < 8; i++) {
        int k = kb * 32 + kk + i * 4;
        s[kk + i * 4][d] = V[(size_t)k * 3072 + d];
    }
    __syncthreads();
    float* out = g_vt + (size_t)z * (DH_ * LI_) + kb * 32;
    const int ko = t & 31, dw = t >> 5;
    #pragma unroll
    for (int i = 0; i < 8; i++) {
        int dd = dw + i * 8;
        out[(size_t)dd * LI_ + ko] = s[ko][dd];
    }
}

// ======================================================================
// RoPE
// ======================================================================
__global__ void k_rope(const float* __restrict__ rope)
{
    __shared__ float cs[32], sns[32];
    int s = blockIdx.x;
    int t = threadIdx.x;
    if (t < 32) {
        float ang = rope[(size_t)s * 32 + t];
        cs[t] = cosf(ang);
        sns[t] = sinf(ang);
    }
    __syncthreads();
    int h = t >> 5, d = t & 31;
    float c = cs[d], sn = sns[d];
    float* q = g_qkv + (size_t)s * 3072 + h * 64;
    float* k = q + 1024;
    float q1 = q[d], q2 = q[d + 32];
    q[d]      = q1 * c - q2 * sn;
    q[d + 32] = q2 * c + q1 * sn;
    float k1 = k[d], k2 = k[d + 32];
    k[d]      = k1 * c - k2 * sn;
    k[d + 32] = k2 * c + k1 * sn;
}

// ======================================================================
// Launch: parallel chains. Launch #4 (code order) = a 1-block k_flash
// writing to g_dump — pure profiling probe, output never consumed.
// ======================================================================
extern "C" void kernel_launch(void* const* d_in, const int* in_sizes, int n_in,
                              void* d_out, int out_size)
{
    const float* hs     = (const float*)d_in[0];
    const int*   coords = (const int*)  d_in[1];
    const float* rope   = (const float*)d_in[3];
    const float* Wq_idx = (const float*)d_in[4];
    const float* Wk_idx = (const float*)d_in[5];
    const float* W1g    = (const float*)d_in[6];
    const float* b1g    = (const float*)d_in[7];
    const float* W2g    = (const float*)d_in[8];
    const float* b2g    = (const float*)d_in[9];
    const float* rpe    = (const float*)d_in[10];
    const float* Wqkv_d = (const float*)d_in[11];
    const float* bqkv_d = (const float*)d_in[12];
    const float* Wqkv_u = (const float*)d_in[13];
    const float* bqkv_u = (const float*)d_in[14];
    const float* Wp_d   = (const float*)d_in[15];
    const float* bp_d   = (const float*)d_in[16];
    const float* Wp_u   = (const float*)d_in[17];
    const float* bp_u   = (const float*)d_in[18];
    const float* scaler = (const float*)d_in[19];
    float* out = (float*)d_out;

    float *tmp1, *qkv, *attout, *tmp2, *dump;
    cudaGetSymbolAddress((void**)&tmp1,   g_tmp1);
    cudaGetSymbolAddress((void**)&qkv,    g_qkv);
    cudaGetSymbolAddress((void**)&attout, g_attout);
    cudaGetSymbolAddress((void**)&tmp2,   g_tmp2);
    cudaGetSymbolAddress((void**)&dump,   g_dump);

    const int dyn64  = (2 * 128 + 2 * 64)  * AST * 4;
    const int dynFl  = (128 * 68 + 64 * 68 + 64 * 68) * 4 + 128 * 16 * 4;
    const int dynIS  = (128 * 128 + 8 * 128 + 520 + 32 + 32 + 8 + 4) * 4 + 512 * 4 + 8 * 4;
    cudaFuncSetAttribute((const void*)k_mma_gemm<64,4,2>,  cudaFuncAttributeMaxDynamicSharedMemorySize, dyn64);
    cudaFuncSetAttribute((const void*)k_flash, cudaFuncAttributeMaxDynamicSharedMemorySize, dynFl);
    cudaFuncSetAttribute((const void*)k_idx_scores, cudaFuncAttributeMaxDynamicSharedMemorySize, dynIS);

    static cudaStream_t sB = [](){
        cudaStream_t s; cudaStreamCreateWithFlags(&s, cudaStreamNonBlocking); return s;
    }();
    static cudaStream_t sC = [](){
        cudaStream_t s; cudaStreamCreateWithFlags(&s, cudaStreamNonBlocking); return s;
    }();
    static cudaEvent_t eFork = [](){
        cudaEvent_t e; cudaEventCreateWithFlags(&e, cudaEventDisableTiming); return e;
    }();
    static cudaEvent_t eJoin = [](){
        cudaEvent_t e; cudaEventCreateWithFlags(&e, cudaEventDisableTiming); return e;
    }();
    static cudaEvent_t eJoinC = [](){
        cudaEvent_t e; cudaEventCreateWithFlags(&e, cudaEventDisableTiming); return e;
    }();

    cudaEventRecord(eFork, 0);
    cudaStreamWaitEvent(sB, eFork, 0);
    cudaStreamWaitEvent(sC, eFork, 0);

    // (1-3) chain B
    k_mma_gemm<64,4,2><<<dim3(4, 16), 256, dyn64, sB>>>(
        hs, DIM_, Wqkv_d, DIM_, tmp1, BOT_, DIM_, bqkv_d, nullptr);
    k_mma_gemm<64,4,2><<<dim3(48, 16), 256, dyn64, sB>>>(
        tmp1, BOT_, Wqkv_u, BOT_, qkv, 3 * DIM_, BOT_, bqkv_u, nullptr);
    k_vt<<<dim3(NIMG_ * H_, 16), 256, 0, sB>>>();
    // (4) 1-block flash probe -> g_dump (ncu slot; output never consumed)
    k_flash<<<dim3(1, 1), 256, dynFl, sC>>>(dump);
    // (5) chain A
    k_idxproj<<<dim3(4, 32), 256>>>(hs, Wq_idx, Wk_idx);
    // (6) chain B
    k_rope<<<S_, 512, 0, sB>>>(rope);
    // (7-8) chain A
    k_idx_scores<<<256, 256, dynIS>>>(coords, W1g, b1g, W2g, b2g, rpe);
    k_topk<<<S_, 256>>>();

    cudaEventRecord(eJoin, sB);
    cudaStreamWaitEvent(0, eJoin, 0);

    // (9) flash
    k_flash<<<dim3(4, NIMG_ * H_), 256, dynFl>>>(attout);

    // (10-11) final projections
    k_mma_gemm<64,4,2><<<dim3(4, 16), 256, dyn64>>>(
        attout, DIM_, Wp_d, DIM_, tmp2, BOT_, DIM_, bp_d, nullptr);
    k_mma_gemm<64,4,2><<<dim3(16, 16), 256, dyn64>>>(
        tmp2, BOT_, Wp_u, BOT_, out, DIM_, BOT_, bp_u, scaler);

    // join probe stream back into the graph
    cudaEventRecord(eJoinC, sC);
    cudaStreamWaitEvent(0, eJoinC, 0);
}